// round 13
// baseline (speedup 1.0000x reference)
#include <cuda_runtime.h>
#include <cuda_bf16.h>
#include <math.h>
#include <stdint.h>

#define NMAX 20000
#define EMAX 60000
#define EHMAX 30000
#define ML 128

// ---------------- scratch (static __device__ — no runtime alloc) ----------------
__device__ unsigned short g_hi[2][NMAX * ML], g_lo[2][NMAX * ML];
__device__ unsigned short z_hi[2][EMAX * ML], z_lo[2][EMAX * ML];
__device__ unsigned short agg_hi[NMAX * ML], agg_lo[NMAX * ML];
__device__ float dot_buf[EMAX];
__device__ float qhat_d[EMAX];
__device__ float qtilde_d[EMAX];
__device__ float qhatdir_d[EHMAX];
__device__ float dhat_d[NMAX];
__device__ float hbuf[2][NMAX];
__device__ float r_d[EMAX], pump_d[EMAX], c0_d[EMAX], c1_d[EMAX], c2_d[EMAX];
__device__ float hstar_d[NMAX], dstar_d[NMAX], resm_d[NMAX];
__device__ int   csr_off[NMAX], csr_cnt[NMAX], csr_cur[NMAX], csr_edge[EMAX];
__device__ int   csr_sndr_d[EMAX];
__device__ float csr_loss_d[EMAX];
__device__ int   known_cum;
__device__ unsigned int bar_cnt, bar_epoch;

// transposed + split weights: [n][k] layout, bf16 hi / lo
#define WT_TOTAL 278528
__device__ unsigned short wt_hi[WT_TOTAL];
__device__ unsigned short wt_lo[WT_TOTAL];
#define OFF_E1_0 0
#define OFF_E1_1 49152
#define OFF_E2_0 98304
#define OFF_E2_1 114688
#define OFF_N1_0 131072
#define OFF_N1_1 163840
#define OFF_N2_0 196608
#define OFF_N2_1 212992
#define OFF_Z    229376

// ---------------- bf16 split helpers ----------------
__device__ __forceinline__ void split2(float v, unsigned short& h, unsigned short& l) {
    __nv_bfloat16 bh = __float2bfloat16_rn(v);
    h = __bfloat16_as_ushort(bh);
    float resid = v - __bfloat162float(bh);
    l = __bfloat16_as_ushort(__float2bfloat16_rn(resid));
}
__device__ __forceinline__ uint32_t bf16x2_pack(float hi, float lo) {
    uint32_t r;
    asm("cvt.rn.bf16x2.f32 %0, %1, %2;" : "=r"(r) : "f"(hi), "f"(lo));
    return r;
}
__device__ __forceinline__ void split2x2(float v0, float v1, uint32_t& hw, uint32_t& lw) {
    hw = bf16x2_pack(v1, v0);
    float h0 = __uint_as_float(hw << 16);
    float h1 = __uint_as_float(hw & 0xffff0000u);
    lw = bf16x2_pack(v1 - h1, v0 - h0);
}
__device__ __forceinline__ void splitpack16(const float* v, uint4& h0, uint4& h1,
                                            uint4& l0, uint4& l1) {
    uint32_t hw[8], lw[8];
#pragma unroll
    for (int j = 0; j < 8; j++)
        split2x2(v[2 * j], v[2 * j + 1], hw[j], lw[j]);
    h0 = make_uint4(hw[0], hw[1], hw[2], hw[3]);
    h1 = make_uint4(hw[4], hw[5], hw[6], hw[7]);
    l0 = make_uint4(lw[0], lw[1], lw[2], lw[3]);
    l1 = make_uint4(lw[4], lw[5], lw[6], lw[7]);
}

__device__ __forceinline__ void mma_bf16(float c[4], const uint32_t a[4], const uint32_t b[2]) {
    asm volatile(
        "mma.sync.aligned.m16n8k16.row.col.f32.bf16.bf16.f32 "
        "{%0,%1,%2,%3}, {%4,%5,%6,%7}, {%8,%9}, {%0,%1,%2,%3};\n"
        : "+f"(c[0]), "+f"(c[1]), "+f"(c[2]), "+f"(c[3])
        : "r"(a[0]), "r"(a[1]), "r"(a[2]), "r"(a[3]), "r"(b[0]), "r"(b[1]));
}

__device__ __forceinline__ void ldsm4(uint32_t* r, const unsigned short* p) {
    uint32_t a = (uint32_t)__cvta_generic_to_shared(p);
    asm volatile("ldmatrix.sync.aligned.m8n8.x4.shared.b16 {%0,%1,%2,%3}, [%4];"
                 : "=r"(r[0]), "=r"(r[1]), "=r"(r[2]), "=r"(r[3]) : "r"(a));
}

// cp.async 16B global->shared
__device__ __forceinline__ void cpa16(unsigned short* dst, const unsigned short* src) {
    uint32_t d = (uint32_t)__cvta_generic_to_shared(dst);
    asm volatile("cp.async.cg.shared.global [%0], [%1], 16;" :: "r"(d), "l"(src));
}
#define CPA_COMMIT() asm volatile("cp.async.commit_group;" ::: "memory")
#define CPA_WAIT0()  asm volatile("cp.async.wait_group 0;" ::: "memory")

// ---- smem geometry (R11 layout: separate H, 1 CTA/SM) ----
#define PA 40
#define PB 40
#define PH 136
#define A_U16 (128 * PA)
#define B_U16 (128 * PB)
#define H_U16 (128 * PH)
#define SMEM_MLP  ((4 * A_U16 + 4 * B_U16 + 2 * H_U16) * 2)
#define SMEM_ZB   ((4 * A_U16 + 4 * B_U16) * 2)

// one k16 step of split-bf16 mma using ldmatrix.x4 fragment loads
__device__ __forceinline__ void k16_step(
    float acc[4][4][4],
    const unsigned short* __restrict__ Ah_, const unsigned short* __restrict__ Al_,
    int pa, int ka,
    const unsigned short* __restrict__ Bh_, const unsigned short* __restrict__ Bl_,
    int kb, int wm, int wn, int lane)
{
    int l7 = lane & 7, lb3 = (lane >> 3) & 1, lb4 = lane >> 4;
    uint32_t ah[4][4], al[4][4], bh[4][2], bl[4][2];
    int arow = wm * 64 + l7 + lb3 * 8;
    int akof = ka + lb4 * 8;
#pragma unroll
    for (int mf = 0; mf < 4; mf++) {
        ldsm4(ah[mf], Ah_ + (arow + mf * 16) * pa + akof);
        ldsm4(al[mf], Al_ + (arow + mf * 16) * pa + akof);
    }
    int brow = wn * 32 + l7 + lb4 * 8;
    int bkof = kb + lb3 * 8;
#pragma unroll
    for (int h = 0; h < 2; h++) {
        uint32_t t[4];
        ldsm4(t, Bh_ + (brow + h * 16) * PB + bkof);
        bh[2 * h][0] = t[0]; bh[2 * h][1] = t[1];
        bh[2 * h + 1][0] = t[2]; bh[2 * h + 1][1] = t[3];
        ldsm4(t, Bl_ + (brow + h * 16) * PB + bkof);
        bl[2 * h][0] = t[0]; bl[2 * h][1] = t[1];
        bl[2 * h + 1][0] = t[2]; bl[2 * h + 1][1] = t[3];
    }
#pragma unroll
    for (int mf = 0; mf < 4; mf++)
#pragma unroll
        for (int nf = 0; nf < 4; nf++) {
            mma_bf16(acc[mf][nf], al[mf], bh[nf]);
            mma_bf16(acc[mf][nf], ah[mf], bl[nf]);
            mma_bf16(acc[mf][nf], ah[mf], bh[nf]);
        }
}

// ---------------- weight prep ----------------
__global__ void wprep_all(const float* __restrict__ We1, const float* __restrict__ We2,
                          const float* __restrict__ Wn1, const float* __restrict__ Wn2,
                          const float* __restrict__ Wz) {
    int i = blockIdx.x * blockDim.x + threadIdx.x;
    if (i >= WT_TOTAL) return;
    const float* W; int Kd, off, li;
    if (i < 98304)       { li = i;          W = We1; Kd = 384; off = OFF_E1_0;
                           if (li >= 49152) { W = We1 + 49152; off = OFF_E1_1; li -= 49152; } }
    else if (i < 131072) { li = i - 98304;  W = We2; Kd = 128; off = OFF_E2_0;
                           if (li >= 16384) { W = We2 + 16384; off = OFF_E2_1; li -= 16384; } }
    else if (i < 196608) { li = i - 131072; W = Wn1; Kd = 256; off = OFF_N1_0;
                           if (li >= 32768) { W = Wn1 + 32768; off = OFF_N1_1; li -= 32768; } }
    else if (i < 229376) { li = i - 196608; W = Wn2; Kd = 128; off = OFF_N2_0;
                           if (li >= 16384) { W = Wn2 + 16384; off = OFF_N2_1; li -= 16384; } }
    else                 { li = i - 229376; W = Wz;  Kd = 384; off = OFF_Z; }
    int k = li >> 7, n = li & 127;
    unsigned short h, l;
    split2(W[li], h, l);
    wt_hi[off + (size_t)n * Kd + k] = h;
    wt_lo[off + (size_t)n * Kd + k] = l;
}

// ---------------- setup kernels ----------------
__global__ void pack_kernel(const float* __restrict__ x, const float* __restrict__ ea,
                            int N, int E, int Eh) {
    int i = blockIdx.x * blockDim.x + threadIdx.x;
    if (i < E) {
        r_d[i]    = ea[i * 8 + 0];
        pump_d[i] = ea[i * 8 + 3];
        c0_d[i]   = ea[i * 8 + 4];
        c1_d[i]   = ea[i * 8 + 5];
        c2_d[i]   = ea[i * 8 + 6];
        qhat_d[i] = 0.f;
        qtilde_d[i] = 0.f;
        if (i < Eh) qhatdir_d[i] = 0.f;
    }
    if (i < N) {
        hstar_d[i] = x[i * 5 + 0];
        dstar_d[i] = x[i * 5 + 1];
        resm_d[i]  = x[i * 5 + 4];
        dhat_d[i]  = 0.f;
        csr_cnt[i] = 0;
    }
}

__global__ void csr_count_kernel(const int* __restrict__ rcvr, int E) {
    int e = blockIdx.x * blockDim.x + threadIdx.x;
    if (e < E) atomicAdd(&csr_cnt[rcvr[e]], 1);
}

__global__ void csr_scan_kernel(int N) {
    __shared__ int wsum[32];
    int t = threadIdx.x;
    int C = (N + 1023) >> 10;
    int beg = t * C;
    int end = beg + C; if (end > N) end = N;
    int s = 0;
    for (int i = beg; i < end; i++) s += csr_cnt[i];
    int lane = t & 31, w = t >> 5;
    int v = s;
    for (int o = 1; o < 32; o <<= 1) {
        int u = __shfl_up_sync(0xffffffffu, v, o);
        if (lane >= o) v += u;
    }
    if (lane == 31) wsum[w] = v;
    __syncthreads();
    if (w == 0) {
        int vv = wsum[lane];
        for (int o = 1; o < 32; o <<= 1) {
            int u = __shfl_up_sync(0xffffffffu, vv, o);
            if (lane >= o) vv += u;
        }
        wsum[lane] = vv;
    }
    __syncthreads();
    int base = (w > 0 ? wsum[w - 1] : 0) + (v - s);
    int run = base;
    for (int i = beg; i < end; i++) {
        csr_off[i] = run;
        csr_cur[i] = run;
        run += csr_cnt[i];
    }
}

__global__ void csr_fill_kernel(const int* __restrict__ rcvr, const int* __restrict__ sndr, int E) {
    int e = blockIdx.x * blockDim.x + threadIdx.x;
    if (e < E) {
        int pos = atomicAdd(&csr_cur[rcvr[e]], 1);
        csr_edge[pos] = e;
        csr_sndr_d[pos] = sndr[e];
    }
}

// ---------------- edge MLP ----------------
template<bool L0>
__global__ __launch_bounds__(256, 1) void edge_mlp_tc(
    int w1off, int w2off,
    const int* __restrict__ sndr, const int* __restrict__ rcvr,
    int gp, int zin_p, int zout_p, int E,
    const float* __restrict__ Wni, const float* __restrict__ Wedge) {
    extern __shared__ unsigned short smu[];
    unsigned short* Ah = smu;
    unsigned short* Al = smu + 2 * A_U16;
    unsigned short* Bh = smu + 4 * A_U16;
    unsigned short* Bl = smu + 4 * A_U16 + 2 * B_U16;
    unsigned short* Hh = smu + 4 * A_U16 + 4 * B_U16;
    unsigned short* Hl = Hh + H_U16;
    __shared__ float wext[L0 ? 640 : 1];

    int tid = threadIdx.x;
    int wid = tid >> 5, lane = tid & 31;
    int g = lane >> 2, tg = lane & 3;
    int wm = wid >> 2, wn = wid & 3;
    int row0 = blockIdx.x * 128;

    int r = tid >> 1;
    int kh = (tid & 1) * 16;
    int eix = row0 + r; if (eix >= E) eix = E - 1;
    int sr = sndr[eix], rr = rcvr[eix];

    if (L0) {
        for (int j = tid; j < 384; j += 256) wext[j] = Wni[j];
        if (tid < 256) wext[384 + tid] = Wedge[tid];
        __syncthreads();
    }

    const unsigned short* gh = g_hi[gp];
    const unsigned short* gl = g_lo[gp];
    const unsigned short* zh = z_hi[zin_p];
    const unsigned short* zl = z_lo[zin_p];

    float acc[4][4][4];
#pragma unroll
    for (int a = 0; a < 4; a++)
#pragma unroll
        for (int b = 0; b < 4; b++)
#pragma unroll
            for (int q = 0; q < 4; q++) acc[a][b][q] = 0.f;

    float sdh = 0.f, sds = 0.f, srm = 0.f, rdh = 0.f, rds = 0.f, rrm = 0.f, qt = 0.f, qhv = 0.f;
    if (L0) {
        sdh = dhat_d[sr];  sds = dstar_d[sr];  srm = resm_d[sr];
        rdh = dhat_d[rr];  rds = dstar_d[rr];  rrm = resm_d[rr];
        qt = qtilde_d[eix]; qhv = qhat_d[eix];
    }

    auto loadA = [&](int s, int b) {
        int kk = s * 32 + kh;
        unsigned short* a  = Ah + b * A_U16 + r * PA + kh;
        unsigned short* a2 = Al + b * A_U16 + r * PA + kh;
        if (L0) {
            float v[16];
            if (kk < 128) {
#pragma unroll
                for (int j = 0; j < 16; j++)
                    v[j] = sdh * wext[kk + j] + sds * wext[128 + kk + j] + srm * wext[256 + kk + j];
            } else if (kk < 256) {
                int c = kk - 128;
#pragma unroll
                for (int j = 0; j < 16; j++)
                    v[j] = rdh * wext[c + j] + rds * wext[128 + c + j] + rrm * wext[256 + c + j];
            } else {
                int c = kk - 256;
#pragma unroll
                for (int j = 0; j < 16; j++)
                    v[j] = qt * wext[384 + c + j] + qhv * wext[384 + 128 + c + j];
            }
            uint4 h0, h1, l0, l1;
            splitpack16(v, h0, h1, l0, l1);
            *(uint4*)a = h0;  *(uint4*)(a + 8) = h1;
            *(uint4*)a2 = l0; *(uint4*)(a2 + 8) = l1;
        } else {
            const unsigned short *hs, *ls; size_t base;
            if (kk < 128)      { hs = gh; ls = gl; base = (size_t)sr * ML + kk; }
            else if (kk < 256) { hs = gh; ls = gl; base = (size_t)rr * ML + (kk - 128); }
            else               { hs = zh; ls = zl; base = (size_t)eix * ML + (kk - 256); }
            cpa16(a, hs + base);       cpa16(a + 8, hs + base + 8);
            cpa16(a2, ls + base);      cpa16(a2 + 8, ls + base + 8);
        }
    };
    auto loadB = [&](int s, int woff, int Kd, int b) {
        int kk = s * 32 + kh;
        const unsigned short* p = wt_hi + woff + (size_t)r * Kd + kk;
        const unsigned short* q = wt_lo + woff + (size_t)r * Kd + kk;
        unsigned short* d0 = Bh + b * B_U16 + r * PB + kh;
        unsigned short* d1 = Bl + b * B_U16 + r * PB + kh;
        cpa16(d0, p); cpa16(d0 + 8, p + 8);
        cpa16(d1, q); cpa16(d1 + 8, q + 8);
    };

    // stage 1: K = 384, 12 slabs, pipelined with cp.async
    loadA(0, 0); loadB(0, w1off, 384, 0);
    CPA_COMMIT(); CPA_WAIT0();
    __syncthreads();
    for (int s = 0; s < 12; s++) {
        int b = s & 1;
        if (s < 11) { loadA(s + 1, 1 - b); loadB(s + 1, w1off, 384, 1 - b); CPA_COMMIT(); }
        k16_step(acc, Ah + b * A_U16, Al + b * A_U16, PA, 0,
                 Bh + b * B_U16, Bl + b * B_U16, 0, wm, wn, lane);
        k16_step(acc, Ah + b * A_U16, Al + b * A_U16, PA, 16,
                 Bh + b * B_U16, Bl + b * B_U16, 16, wm, wn, lane);
        if (s < 11) CPA_WAIT0();
        __syncthreads();
    }
    // relu -> H (split bf16), reset acc
#pragma unroll
    for (int mf = 0; mf < 4; mf++) {
        int r0 = wm * 64 + mf * 16 + g;
#pragma unroll
        for (int nf = 0; nf < 4; nf++) {
            int c = wn * 32 + nf * 8 + tg * 2;
            uint32_t hw, lw;
            split2x2(fmaxf(acc[mf][nf][0], 0.f), fmaxf(acc[mf][nf][1], 0.f), hw, lw);
            *(uint32_t*)&Hh[r0 * PH + c] = hw;
            *(uint32_t*)&Hl[r0 * PH + c] = lw;
            split2x2(fmaxf(acc[mf][nf][2], 0.f), fmaxf(acc[mf][nf][3], 0.f), hw, lw);
            *(uint32_t*)&Hh[(r0 + 8) * PH + c] = hw;
            *(uint32_t*)&Hl[(r0 + 8) * PH + c] = lw;
            acc[mf][nf][0] = acc[mf][nf][1] = acc[mf][nf][2] = acc[mf][nf][3] = 0.f;
        }
    }
    // stage 2: K = 128, A = H, B pipelined with cp.async
    loadB(0, w2off, 128, 0);
    CPA_COMMIT(); CPA_WAIT0();
    __syncthreads();
    for (int s = 0; s < 4; s++) {
        int b = s & 1;
        if (s < 3) { loadB(s + 1, w2off, 128, 1 - b); CPA_COMMIT(); }
        k16_step(acc, Hh, Hl, PH, 32 * s,
                 Bh + b * B_U16, Bl + b * B_U16, 0, wm, wn, lane);
        k16_step(acc, Hh, Hl, PH, 32 * s + 16,
                 Bh + b * B_U16, Bl + b * B_U16, 16, wm, wn, lane);
        if (s < 3) CPA_WAIT0();
        __syncthreads();
    }
    unsigned short* zoh = z_hi[zout_p];
    unsigned short* zol = z_lo[zout_p];
#pragma unroll
    for (int mf = 0; mf < 4; mf++) {
        int gr = row0 + wm * 64 + mf * 16 + g;
#pragma unroll
        for (int nf = 0; nf < 4; nf++) {
            int c = wn * 32 + nf * 8 + tg * 2;
            uint32_t hw, lw;
            if (gr < E) {
                split2x2(acc[mf][nf][0], acc[mf][nf][1], hw, lw);
                *(uint32_t*)&zoh[(size_t)gr * ML + c] = hw;
                *(uint32_t*)&zol[(size_t)gr * ML + c] = lw;
            }
            if (gr + 8 < E) {
                split2x2(acc[mf][nf][2], acc[mf][nf][3], hw, lw);
                *(uint32_t*)&zoh[(size_t)(gr + 8) * ML + c] = hw;
                *(uint32_t*)&zol[(size_t)(gr + 8) * ML + c] = lw;
            }
        }
    }
}

// ---------------- node MLP ----------------
template<bool L0>
__global__ __launch_bounds__(256, 1) void node_mlp_tc(
    int w1off, int w2off, int gp_in, int gp_out, int N,
    const float* __restrict__ Wni) {
    extern __shared__ unsigned short smu[];
    unsigned short* Ah = smu;
    unsigned short* Al = smu + 2 * A_U16;
    unsigned short* Bh = smu + 4 * A_U16;
    unsigned short* Bl = smu + 4 * A_U16 + 2 * B_U16;
    unsigned short* Hh = smu + 4 * A_U16 + 4 * B_U16;
    unsigned short* Hl = Hh + H_U16;
    __shared__ float wext[L0 ? 384 : 1];

    int tid = threadIdx.x;
    int wid = tid >> 5, lane = tid & 31;
    int g = lane >> 2, tg = lane & 3;
    int wm = wid >> 2, wn = wid & 3;
    int row0 = blockIdx.x * 128;

    int r = tid >> 1;
    int kh = (tid & 1) * 16;
    int er = row0 + r; if (er >= N) er = N - 1;

    if (L0) {
        for (int j = tid; j < 384; j += 256) wext[j] = Wni[j];
        __syncthreads();
    }

    const unsigned short* gh = g_hi[gp_in];
    const unsigned short* gl = g_lo[gp_in];

    float acc[4][4][4];
#pragma unroll
    for (int a = 0; a < 4; a++)
#pragma unroll
        for (int b = 0; b < 4; b++)
#pragma unroll
            for (int q = 0; q < 4; q++) acc[a][b][q] = 0.f;

    float ndh = 0.f, nds = 0.f, nrm = 0.f;
    if (L0) { ndh = dhat_d[er]; nds = dstar_d[er]; nrm = resm_d[er]; }

    auto loadA = [&](int s, int b) {
        int kk = s * 32 + kh;
        unsigned short* a  = Ah + b * A_U16 + r * PA + kh;
        unsigned short* a2 = Al + b * A_U16 + r * PA + kh;
        if (L0 && kk < 128) {
            float v[16];
#pragma unroll
            for (int j = 0; j < 16; j++)
                v[j] = ndh * wext[kk + j] + nds * wext[128 + kk + j] + nrm * wext[256 + kk + j];
            uint4 h0, h1, l0, l1;
            splitpack16(v, h0, h1, l0, l1);
            *(uint4*)a = h0;  *(uint4*)(a + 8) = h1;
            *(uint4*)a2 = l0; *(uint4*)(a2 + 8) = l1;
        } else {
            const unsigned short *hs, *ls; size_t base;
            if (kk < 128) { hs = gh; ls = gl; base = (size_t)er * ML + kk; }
            else          { hs = agg_hi; ls = agg_lo; base = (size_t)er * ML + (kk - 128); }
            cpa16(a, hs + base);  cpa16(a + 8, hs + base + 8);
            cpa16(a2, ls + base); cpa16(a2 + 8, ls + base + 8);
        }
    };
    auto loadB = [&](int s, int woff, int Kd, int b) {
        int kk = s * 32 + kh;
        const unsigned short* p = wt_hi + woff + (size_t)r * Kd + kk;
        const unsigned short* q = wt_lo + woff + (size_t)r * Kd + kk;
        unsigned short* d0 = Bh + b * B_U16 + r * PB + kh;
        unsigned short* d1 = Bl + b * B_U16 + r * PB + kh;
        cpa16(d0, p); cpa16(d0 + 8, p + 8);
        cpa16(d1, q); cpa16(d1 + 8, q + 8);
    };

    // stage 1: K = 256, 8 slabs
    loadA(0, 0); loadB(0, w1off, 256, 0);
    CPA_COMMIT(); CPA_WAIT0();
    __syncthreads();
    for (int s = 0; s < 8; s++) {
        int b = s & 1;
        if (s < 7) { loadA(s + 1, 1 - b); loadB(s + 1, w1off, 256, 1 - b); CPA_COMMIT(); }
        k16_step(acc, Ah + b * A_U16, Al + b * A_U16, PA, 0,
                 Bh + b * B_U16, Bl + b * B_U16, 0, wm, wn, lane);
        k16_step(acc, Ah + b * A_U16, Al + b * A_U16, PA, 16,
                 Bh + b * B_U16, Bl + b * B_U16, 16, wm, wn, lane);
        if (s < 7) CPA_WAIT0();
        __syncthreads();
    }
#pragma unroll
    for (int mf = 0; mf < 4; mf++) {
        int r0 = wm * 64 + mf * 16 + g;
#pragma unroll
        for (int nf = 0; nf < 4; nf++) {
            int c = wn * 32 + nf * 8 + tg * 2;
            uint32_t hw, lw;
            split2x2(fmaxf(acc[mf][nf][0], 0.f), fmaxf(acc[mf][nf][1], 0.f), hw, lw);
            *(uint32_t*)&Hh[r0 * PH + c] = hw;
            *(uint32_t*)&Hl[r0 * PH + c] = lw;
            split2x2(fmaxf(acc[mf][nf][2], 0.f), fmaxf(acc[mf][nf][3], 0.f), hw, lw);
            *(uint32_t*)&Hh[(r0 + 8) * PH + c] = hw;
            *(uint32_t*)&Hl[(r0 + 8) * PH + c] = lw;
            acc[mf][nf][0] = acc[mf][nf][1] = acc[mf][nf][2] = acc[mf][nf][3] = 0.f;
        }
    }
    // stage 2: K = 128
    loadB(0, w2off, 128, 0);
    CPA_COMMIT(); CPA_WAIT0();
    __syncthreads();
    for (int s = 0; s < 4; s++) {
        int b = s & 1;
        if (s < 3) { loadB(s + 1, w2off, 128, 1 - b); CPA_COMMIT(); }
        k16_step(acc, Hh, Hl, PH, 32 * s,
                 Bh + b * B_U16, Bl + b * B_U16, 0, wm, wn, lane);
        k16_step(acc, Hh, Hl, PH, 32 * s + 16,
                 Bh + b * B_U16, Bl + b * B_U16, 16, wm, wn, lane);
        if (s < 3) CPA_WAIT0();
        __syncthreads();
    }
    unsigned short* goh = g_hi[gp_out];
    unsigned short* gol = g_lo[gp_out];
#pragma unroll
    for (int mf = 0; mf < 4; mf++) {
        int gr = row0 + wm * 64 + mf * 16 + g;
#pragma unroll
        for (int nf = 0; nf < 4; nf++) {
            int c = wn * 32 + nf * 8 + tg * 2;
            uint32_t hw, lw;
            if (gr < N) {
                split2x2(acc[mf][nf][0], acc[mf][nf][1], hw, lw);
                *(uint32_t*)&goh[(size_t)gr * ML + c] = hw;
                *(uint32_t*)&gol[(size_t)gr * ML + c] = lw;
            }
            if (gr + 8 < N) {
                split2x2(acc[mf][nf][2], acc[mf][nf][3], hw, lw);
                *(uint32_t*)&goh[(size_t)(gr + 8) * ML + c] = hw;
                *(uint32_t*)&gol[(size_t)(gr + 8) * ML + c] = lw;
            }
        }
    }
}

// ---------------- zbar ----------------
__global__ __launch_bounds__(256, 1) void zbar_tc(
    const float* __restrict__ Wf,
    const int* __restrict__ sndr, const int* __restrict__ rcvr,
    int gp, int zp, int E, int Eh) {
    extern __shared__ unsigned short smu[];
    unsigned short* Ah = smu;
    unsigned short* Al = smu + 2 * A_U16;
    unsigned short* Bh = smu + 4 * A_U16;
    unsigned short* Bl = smu + 4 * A_U16 + 2 * B_U16;
    __shared__ float wfs[256];
    __shared__ float rowsum[128];

    int tid = threadIdx.x;
    int wid = tid >> 5, lane = tid & 31;
    int g = lane >> 2, tg = lane & 3;
    int wm = wid >> 2, wn = wid & 3;
    int row0 = blockIdx.x * 128;

    int r = tid >> 1;
    int kh = (tid & 1) * 16;
    int eix = row0 + r; if (eix >= E) eix = E - 1;
    int sr = sndr[eix], rr = rcvr[eix];

    wfs[tid] = Wf[tid];
    if (tid < 128) rowsum[tid] = 0.f;
    __syncthreads();

    const unsigned short* gh = g_hi[gp];
    const unsigned short* gl = g_lo[gp];
    const unsigned short* zh = z_hi[zp];
    const unsigned short* zl = z_lo[zp];

    float acc[4][4][4];
#pragma unroll
    for (int a = 0; a < 4; a++)
#pragma unroll
        for (int b = 0; b < 4; b++)
#pragma unroll
            for (int q = 0; q < 4; q++) acc[a][b][q] = 0.f;

    auto loadA = [&](int s, int b) {
        int kk = s * 32 + kh;
        const unsigned short *hs, *ls; size_t base;
        if (kk < 128)      { hs = gh; ls = gl; base = (size_t)sr * ML + kk; }
        else if (kk < 256) { hs = gh; ls = gl; base = (size_t)rr * ML + (kk - 128); }
        else               { hs = zh; ls = zl; base = (size_t)eix * ML + (kk - 256); }
        unsigned short* a  = Ah + b * A_U16 + r * PA + kh;
        unsigned short* a2 = Al + b * A_U16 + r * PA + kh;
        cpa16(a, hs + base);  cpa16(a + 8, hs + base + 8);
        cpa16(a2, ls + base); cpa16(a2 + 8, ls + base + 8);
    };
    auto loadB = [&](int s, int b) {
        int kk = s * 32 + kh;
        const unsigned short* p = wt_hi + OFF_Z + (size_t)r * 384 + kk;
        const unsigned short* q = wt_lo + OFF_Z + (size_t)r * 384 + kk;
        unsigned short* d0 = Bh + b * B_U16 + r * PB + kh;
        unsigned short* d1 = Bl + b * B_U16 + r * PB + kh;
        cpa16(d0, p); cpa16(d0 + 8, p + 8);
        cpa16(d1, q); cpa16(d1 + 8, q + 8);
    };

    loadA(0, 0); loadB(0, 0);
    CPA_COMMIT(); CPA_WAIT0();
    __syncthreads();
    for (int s = 0; s < 12; s++) {
        int b = s & 1;
        if (s < 11) { loadA(s + 1, 1 - b); loadB(s + 1, 1 - b); CPA_COMMIT(); }
        k16_step(acc, Ah + b * A_U16, Al + b * A_U16, PA, 0,
                 Bh + b * B_U16, Bl + b * B_U16, 0, wm, wn, lane);
        k16_step(acc, Ah + b * A_U16, Al + b * A_U16, PA, 16,
                 Bh + b * B_U16, Bl + b * B_U16, 16, wm, wn, lane);
        if (s < 11) CPA_WAIT0();
        __syncthreads();
    }

    float prt[4][2];
#pragma unroll
    for (int mf = 0; mf < 4; mf++) { prt[mf][0] = 0.f; prt[mf][1] = 0.f; }
#pragma unroll
    for (int mf = 0; mf < 4; mf++) {
        int gr0 = row0 + wm * 64 + mf * 16 + g;
        int gr1 = gr0 + 8;
        int off0 = (gr0 < Eh) ? 0 : 128;
        int off1 = (gr1 < Eh) ? 0 : 128;
#pragma unroll
        for (int nf = 0; nf < 4; nf++) {
            int c = wn * 32 + nf * 8 + tg * 2;
            prt[mf][0] += acc[mf][nf][0] * wfs[off0 + c] + acc[mf][nf][1] * wfs[off0 + c + 1];
            prt[mf][1] += acc[mf][nf][2] * wfs[off1 + c] + acc[mf][nf][3] * wfs[off1 + c + 1];
        }
    }
#pragma unroll
    for (int o = 1; o <= 2; o <<= 1)
#pragma unroll
        for (int mf = 0; mf < 4; mf++) {
            prt[mf][0] += __shfl_xor_sync(0xffffffffu, prt[mf][0], o);
            prt[mf][1] += __shfl_xor_sync(0xffffffffu, prt[mf][1], o);
        }
    __syncthreads();
    if (tg == 0) {
#pragma unroll
        for (int mf = 0; mf < 4; mf++) {
            atomicAdd(&rowsum[wm * 64 + mf * 16 + g], prt[mf][0]);
            atomicAdd(&rowsum[wm * 64 + mf * 16 + g + 8], prt[mf][1]);
        }
    }
    __syncthreads();
    if (tid < 128 && row0 + tid < E) dot_buf[row0 + tid] = rowsum[tid];
}

// ---------------- agg (segment max over split z, split output) ----------------
__global__ void agg_kernel(int zp, int N) {
    int t = blockIdx.x * blockDim.x + threadIdx.x;
    if (t >= N * 32) return;
    int n = t >> 5, c4 = (t & 31) * 4;
    const unsigned short* zh = z_hi[zp];
    const unsigned short* zl = z_lo[zp];
    int off = csr_off[n], cnt = csr_cnt[n];
    float m0 = -3.0e38f, m1 = -3.0e38f, m2 = -3.0e38f, m3 = -3.0e38f;
    for (int i = 0; i < cnt; i++) {
        size_t b = (size_t)csr_edge[off + i] * ML + c4;
        uint2 vh = *(const uint2*)&zh[b];
        uint2 vl = *(const uint2*)&zl[b];
        m0 = fmaxf(m0, __uint_as_float(vh.x << 16) + __uint_as_float(vl.x << 16));
        m1 = fmaxf(m1, __uint_as_float(vh.x & 0xffff0000u) + __uint_as_float(vl.x & 0xffff0000u));
        m2 = fmaxf(m2, __uint_as_float(vh.y << 16) + __uint_as_float(vl.y << 16));
        m3 = fmaxf(m3, __uint_as_float(vh.y & 0xffff0000u) + __uint_as_float(vl.y & 0xffff0000u));
    }
    if (cnt == 0) { m0 = m1 = m2 = m3 = 0.f; }
    uint32_t h0, l0, h1, l1;
    split2x2(m0, m1, h0, l0);
    split2x2(m2, m3, h1, l1);
    *(uint2*)&agg_hi[(size_t)n * ML + c4] = make_uint2(h0, h1);
    *(uint2*)&agg_lo[(size_t)n * ML + c4] = make_uint2(l0, l1);
}

// ---------------- fused heads (persistent grid) ----------------
#define HP_BLOCKS 148

__device__ __forceinline__ void gbar() {
    __syncthreads();
    if (threadIdx.x == 0) {
        unsigned int e = *(volatile unsigned int*)&bar_epoch;
        __threadfence();
        unsigned int a = atomicAdd(&bar_cnt, 1u);
        if (a == gridDim.x - 1) {
            bar_cnt = 0;
            __threadfence();
            atomicAdd(&bar_epoch, 1u);
        } else {
            while (*(volatile unsigned int*)&bar_epoch == e) { }
        }
    }
    __syncthreads();
}

__global__ __launch_bounds__(256) void heads_fused(
    const int* __restrict__ sndr, const int* __restrict__ rcvr,
    int N, int E, int Eh, int do_tail, float* __restrict__ out) {
    int gtid = blockIdx.x * blockDim.x + threadIdx.x;
    int gsz = gridDim.x * blockDim.x;

    for (int i = gtid; i < Eh; i += gsz) {
        float qd = qhatdir_d[i] + dot_buf[i] + dot_buf[i + Eh];
        float pd = pump_d[Eh + i];
        if (pd == 1.0f) qd = fminf(qd, 0.f);
        if (pd == 2.0f) qd = 0.f;
        qhatdir_d[i] = qd;
        qhat_d[i] = qd;
        qhat_d[i + Eh] = -qd;
    }
    if (gtid == 0) known_cum = 0;
    gbar();

    for (int p = gtid; p < E; p += gsz) {
        int e = csr_edge[p];
        float q = __ldcg(&qhat_d[e]);
        float q2 = q * q + 1e-24f;
        float lp = r_d[e] * q * __powf(q2, 0.426f);
        float lpu = -(c0_d[e] - c1_d[e] * __powf(q2, c2_d[e] * 0.5f));
        csr_loss_d[p] = (pump_d[e] != 0.f) ? lpu : lp;
    }
    for (int n = gtid; n < N; n += gsz)
        hbuf[0][n] = (resm_d[n] > 0.5f) ? hstar_d[n] : -1.0e30f;
    gbar();

    int off = 0, cnt = 0;
    if (gtid < N) { off = csr_off[gtid]; cnt = csr_cnt[gtid]; }
    int prev = 0;
    int p = 0;
    for (int t = 0; t < 20; t++) {
        if (gtid < N) {
            float hv = hbuf[p][gtid];
            if (hv > -5.0e8f) {
                hbuf[1 - p][gtid] = hv;
            } else {
                float m = -3.0e38f;
                for (int i = off; i < off + cnt; i++) {
                    float hs = __ldcg(&hbuf[p][csr_sndr_d[i]]);
                    m = fmaxf(m, hs - csr_loss_d[i]);
                }
                if (m > -5.0e8f) {
                    hbuf[1 - p][gtid] = m;
                    atomicAdd(&known_cum, 1);
                } else {
                    hbuf[1 - p][gtid] = hv;
                }
            }
        }
        p = 1 - p;
        gbar();
        int c = *(volatile int*)&known_cum;
        if (c == prev) break;
        prev = c;
    }
    if (!do_tail) {
        for (int n = gtid; n < N; n += gsz) {
            float hv = hbuf[p][n];
            out[n] = (hv > -5.0e8f) ? hv : 0.f;
        }
        return;
    }
    for (int n = gtid; n < N; n += gsz) {
        float hv = hbuf[p][n];
        hbuf[0][n] = (hv > -5.0e8f) ? hv : 0.f;
    }
    gbar();
    for (int e = gtid; e < E; e += gsz) {
        float hs = __ldcg(&hbuf[0][sndr[e]]);
        float hr = __ldcg(&hbuf[0][rcvr[e]]);
        float dh = hs - hr;
        float q = dh * __powf(dh * dh + 1e-24f, -0.23f) / __powf(r_d[e], 0.54f);
        float pe = pump_d[e];
        if (pe != 0.f) q = 0.f;
        qtilde_d[e] = q;
        if (fabsf(pe) == 1.0f) qhat_d[e] = q;
    }
    gbar();
    for (int n = gtid; n < N; n += gsz) {
        int o = csr_off[n], c2 = csr_cnt[n];
        float s = 0.f;
        for (int i = 0; i < c2; i++) s += __ldcg(&qhat_d[csr_edge[o + i]]);
        dhat_d[n] = s;
    }
}

// ---------------- launch ----------------
extern "C" void kernel_launch(void* const* d_in, const int* in_sizes, int n_in,
                              void* d_out, int out_size) {
    const float* x     = (const float*)d_in[0];
    const float* ea    = (const float*)d_in[1];
    const float* Wni   = (const float*)d_in[2];
    const float* Wedge = (const float*)d_in[3];
    const float* Wz    = (const float*)d_in[4];
    const float* Wf    = (const float*)d_in[5];
    const float* We1   = (const float*)d_in[6];
    const float* We2   = (const float*)d_in[7];
    const float* Wn1   = (const float*)d_in[8];
    const float* Wn2   = (const float*)d_in[9];
    const int*   ei    = (const int*)d_in[10];

    int N  = in_sizes[0] / 5;
    int E  = in_sizes[10] / 2;
    int Eh = E / 2;
    const int* sndr = ei;
    const int* rcvr = ei + E;
    const int K = 3;  // r_iter=1 + n_iter=2 (fixed by dataset)
    const int TB = 256;
    int mNE = N > E ? N : E;

    cudaFuncSetAttribute(edge_mlp_tc<true>,  cudaFuncAttributeMaxDynamicSharedMemorySize, SMEM_MLP);
    cudaFuncSetAttribute(edge_mlp_tc<false>, cudaFuncAttributeMaxDynamicSharedMemorySize, SMEM_MLP);
    cudaFuncSetAttribute(node_mlp_tc<true>,  cudaFuncAttributeMaxDynamicSharedMemorySize, SMEM_MLP);
    cudaFuncSetAttribute(node_mlp_tc<false>, cudaFuncAttributeMaxDynamicSharedMemorySize, SMEM_MLP);
    cudaFuncSetAttribute(zbar_tc,            cudaFuncAttributeMaxDynamicSharedMemorySize, SMEM_ZB);

    pack_kernel<<<(mNE + TB - 1) / TB, TB>>>(x, ea, N, E, Eh);
    csr_count_kernel<<<(E + TB - 1) / TB, TB>>>(rcvr, E);
    csr_scan_kernel<<<1, 1024>>>(N);
    csr_fill_kernel<<<(E + TB - 1) / TB, TB>>>(rcvr, sndr, E);
    wprep_all<<<(WT_TOTAL + TB - 1) / TB, TB>>>(We1, We2, Wn1, Wn2, Wz);

    int gE = (E + 127) / 128;
    int gN = (N + 127) / 128;
    const int we1off[2] = {OFF_E1_0, OFF_E1_1};
    const int we2off[2] = {OFF_E2_0, OFF_E2_1};
    const int wn1off[2] = {OFF_N1_0, OFF_N1_1};
    const int wn2off[2] = {OFF_N2_0, OFF_N2_1};

    for (int k = 0; k < K; k++) {
        int gp = 0, zp = 0;
        for (int i = 0; i < 2; i++) {
            if (i == 0)
                edge_mlp_tc<true><<<gE, 256, SMEM_MLP>>>(we1off[i], we2off[i],
                                                         sndr, rcvr, gp, zp, 1 - zp, E, Wni, Wedge);
            else
                edge_mlp_tc<false><<<gE, 256, SMEM_MLP>>>(we1off[i], we2off[i],
                                                          sndr, rcvr, gp, zp, 1 - zp, E, Wni, Wedge);
            agg_kernel<<<(N * 32 + TB - 1) / TB, TB>>>(1 - zp, N);
            if (i == 0)
                node_mlp_tc<true><<<gN, 256, SMEM_MLP>>>(wn1off[i], wn2off[i], gp, 1 - gp, N, Wni);
            else
                node_mlp_tc<false><<<gN, 256, SMEM_MLP>>>(wn1off[i], wn2off[i], gp, 1 - gp, N, Wni);
            gp = 1 - gp;
            zp = 1 - zp;
        }
        zbar_tc<<<gE, 256, SMEM_ZB>>>(Wf, sndr, rcvr, gp, zp, E, Eh);
        heads_fused<<<HP_BLOCKS, 256>>>(sndr, rcvr, N, E, Eh, (k < K - 1) ? 1 : 0, (float*)d_out);
    }
}

// round 14
// speedup vs baseline: 1.0831x; 1.0831x over previous
#include <cuda_runtime.h>
#include <cuda_bf16.h>
#include <math.h>
#include <stdint.h>

#define NMAX 20000
#define EMAX 60000
#define EHMAX 30000
#define ML 128

// ---------------- scratch (static __device__ — no runtime alloc) ----------------
__device__ unsigned short g_hi[2][NMAX * ML], g_lo[2][NMAX * ML];
__device__ unsigned short z_hi[2][EMAX * ML], z_lo[2][EMAX * ML];
__device__ unsigned short agg_hi[NMAX * ML], agg_lo[NMAX * ML];
__device__ float dot_buf[EMAX];
__device__ float qhat_d[EMAX];
__device__ float qtilde_d[EMAX];
__device__ float qhatdir_d[EHMAX];
__device__ float dhat_d[NMAX];
__device__ float hbuf[2][NMAX];
__device__ float r_d[EMAX], pump_d[EMAX], c0_d[EMAX], c1_d[EMAX], c2_d[EMAX];
__device__ float hstar_d[NMAX], dstar_d[NMAX], resm_d[NMAX];
__device__ int   csr_off[NMAX], csr_cnt[NMAX], csr_cur[NMAX], csr_edge[EMAX];
__device__ int   csr_sndr_d[EMAX];
__device__ float csr_loss_d[EMAX];
__device__ int   known_cum;
__device__ int   nres_d;
__device__ unsigned int bar_cnt, bar_epoch;

// transposed + split weights: [n][k] layout, bf16 hi / lo
#define WT_TOTAL 278528
__device__ unsigned short wt_hi[WT_TOTAL];
__device__ unsigned short wt_lo[WT_TOTAL];
#define OFF_E1_0 0
#define OFF_E1_1 49152
#define OFF_E2_0 98304
#define OFF_E2_1 114688
#define OFF_N1_0 131072
#define OFF_N1_1 163840
#define OFF_N2_0 196608
#define OFF_N2_1 212992
#define OFF_Z    229376

// ---------------- bf16 split helpers ----------------
__device__ __forceinline__ void split2(float v, unsigned short& h, unsigned short& l) {
    __nv_bfloat16 bh = __float2bfloat16_rn(v);
    h = __bfloat16_as_ushort(bh);
    float resid = v - __bfloat162float(bh);
    l = __bfloat16_as_ushort(__float2bfloat16_rn(resid));
}
__device__ __forceinline__ uint32_t bf16x2_pack(float hi, float lo) {
    uint32_t r;
    asm("cvt.rn.bf16x2.f32 %0, %1, %2;" : "=r"(r) : "f"(hi), "f"(lo));
    return r;
}
__device__ __forceinline__ void split2x2(float v0, float v1, uint32_t& hw, uint32_t& lw) {
    hw = bf16x2_pack(v1, v0);
    float h0 = __uint_as_float(hw << 16);
    float h1 = __uint_as_float(hw & 0xffff0000u);
    lw = bf16x2_pack(v1 - h1, v0 - h0);
}
__device__ __forceinline__ void splitpack16(const float* v, uint4& h0, uint4& h1,
                                            uint4& l0, uint4& l1) {
    uint32_t hw[8], lw[8];
#pragma unroll
    for (int j = 0; j < 8; j++)
        split2x2(v[2 * j], v[2 * j + 1], hw[j], lw[j]);
    h0 = make_uint4(hw[0], hw[1], hw[2], hw[3]);
    h1 = make_uint4(hw[4], hw[5], hw[6], hw[7]);
    l0 = make_uint4(lw[0], lw[1], lw[2], lw[3]);
    l1 = make_uint4(lw[4], lw[5], lw[6], lw[7]);
}

__device__ __forceinline__ void mma_bf16(float c[4], const uint32_t a[4], const uint32_t b[2]) {
    asm volatile(
        "mma.sync.aligned.m16n8k16.row.col.f32.bf16.bf16.f32 "
        "{%0,%1,%2,%3}, {%4,%5,%6,%7}, {%8,%9}, {%0,%1,%2,%3};\n"
        : "+f"(c[0]), "+f"(c[1]), "+f"(c[2]), "+f"(c[3])
        : "r"(a[0]), "r"(a[1]), "r"(a[2]), "r"(a[3]), "r"(b[0]), "r"(b[1]));
}

__device__ __forceinline__ void ldsm4(uint32_t* r, const unsigned short* p) {
    uint32_t a = (uint32_t)__cvta_generic_to_shared(p);
    asm volatile("ldmatrix.sync.aligned.m8n8.x4.shared.b16 {%0,%1,%2,%3}, [%4];"
                 : "=r"(r[0]), "=r"(r[1]), "=r"(r[2]), "=r"(r[3]) : "r"(a));
}

// ---- smem geometry ----
#define PA 40
#define PB 40
#define PH 136
#define A_U16 (128 * PA)
#define B_U16 (128 * PB)
#define H_U16 (128 * PH)
#define SMEM_MLP  ((4 * A_U16 + 4 * B_U16 + 2 * H_U16) * 2)
#define SMEM_ZB   ((4 * A_U16 + 4 * B_U16) * 2)

// one k16 step of split-bf16 mma using ldmatrix.x4 fragment loads
__device__ __forceinline__ void k16_step(
    float acc[4][4][4],
    const unsigned short* __restrict__ Ah_, const unsigned short* __restrict__ Al_,
    int pa, int ka,
    const unsigned short* __restrict__ Bh_, const unsigned short* __restrict__ Bl_,
    int kb, int wm, int wn, int lane)
{
    int l7 = lane & 7, lb3 = (lane >> 3) & 1, lb4 = lane >> 4;
    uint32_t ah[4][4], al[4][4], bh[4][2], bl[4][2];
    int arow = wm * 64 + l7 + lb3 * 8;
    int akof = ka + lb4 * 8;
#pragma unroll
    for (int mf = 0; mf < 4; mf++) {
        ldsm4(ah[mf], Ah_ + (arow + mf * 16) * pa + akof);
        ldsm4(al[mf], Al_ + (arow + mf * 16) * pa + akof);
    }
    int brow = wn * 32 + l7 + lb4 * 8;
    int bkof = kb + lb3 * 8;
#pragma unroll
    for (int h = 0; h < 2; h++) {
        uint32_t t[4];
        ldsm4(t, Bh_ + (brow + h * 16) * PB + bkof);
        bh[2 * h][0] = t[0]; bh[2 * h][1] = t[1];
        bh[2 * h + 1][0] = t[2]; bh[2 * h + 1][1] = t[3];
        ldsm4(t, Bl_ + (brow + h * 16) * PB + bkof);
        bl[2 * h][0] = t[0]; bl[2 * h][1] = t[1];
        bl[2 * h + 1][0] = t[2]; bl[2 * h + 1][1] = t[3];
    }
#pragma unroll
    for (int mf = 0; mf < 4; mf++)
#pragma unroll
        for (int nf = 0; nf < 4; nf++) {
            mma_bf16(acc[mf][nf], al[mf], bh[nf]);
            mma_bf16(acc[mf][nf], ah[mf], bl[nf]);
            mma_bf16(acc[mf][nf], ah[mf], bh[nf]);
        }
}

// ---------------- weight prep ----------------
__global__ void wprep_all(const float* __restrict__ We1, const float* __restrict__ We2,
                          const float* __restrict__ Wn1, const float* __restrict__ Wn2,
                          const float* __restrict__ Wz) {
    int i = blockIdx.x * blockDim.x + threadIdx.x;
    if (i >= WT_TOTAL) return;
    const float* W; int Kd, off, li;
    if (i < 98304)       { li = i;          W = We1; Kd = 384; off = OFF_E1_0;
                           if (li >= 49152) { W = We1 + 49152; off = OFF_E1_1; li -= 49152; } }
    else if (i < 131072) { li = i - 98304;  W = We2; Kd = 128; off = OFF_E2_0;
                           if (li >= 16384) { W = We2 + 16384; off = OFF_E2_1; li -= 16384; } }
    else if (i < 196608) { li = i - 131072; W = Wn1; Kd = 256; off = OFF_N1_0;
                           if (li >= 32768) { W = Wn1 + 32768; off = OFF_N1_1; li -= 32768; } }
    else if (i < 229376) { li = i - 196608; W = Wn2; Kd = 128; off = OFF_N2_0;
                           if (li >= 16384) { W = Wn2 + 16384; off = OFF_N2_1; li -= 16384; } }
    else                 { li = i - 229376; W = Wz;  Kd = 384; off = OFF_Z; }
    int k = li >> 7, n = li & 127;
    unsigned short h, l;
    split2(W[li], h, l);
    wt_hi[off + (size_t)n * Kd + k] = h;
    wt_lo[off + (size_t)n * Kd + k] = l;
}

// ---------------- setup kernels ----------------
__global__ void pack_kernel(const float* __restrict__ x, const float* __restrict__ ea,
                            int N, int E, int Eh) {
    int i = blockIdx.x * blockDim.x + threadIdx.x;
    if (i == 0) nres_d = 0;
    if (i < E) {
        r_d[i]    = ea[i * 8 + 0];
        pump_d[i] = ea[i * 8 + 3];
        c0_d[i]   = ea[i * 8 + 4];
        c1_d[i]   = ea[i * 8 + 5];
        c2_d[i]   = ea[i * 8 + 6];
        qhat_d[i] = 0.f;
        qtilde_d[i] = 0.f;
        if (i < Eh) qhatdir_d[i] = 0.f;
    }
    if (i < N) {
        hstar_d[i] = x[i * 5 + 0];
        dstar_d[i] = x[i * 5 + 1];
        resm_d[i]  = x[i * 5 + 4];
        dhat_d[i]  = 0.f;
        csr_cnt[i] = 0;
    }
}

__global__ void csr_count_kernel(const int* __restrict__ rcvr, int E, int N) {
    int e = blockIdx.x * blockDim.x + threadIdx.x;
    if (e < E) atomicAdd(&csr_cnt[rcvr[e]], 1);
    if (e < N && resm_d[e] > 0.5f) atomicAdd(&nres_d, 1);
}

__global__ void csr_scan_kernel(int N) {
    __shared__ int wsum[32];
    int t = threadIdx.x;
    int C = (N + 1023) >> 10;
    int beg = t * C;
    int end = beg + C; if (end > N) end = N;
    int s = 0;
    for (int i = beg; i < end; i++) s += csr_cnt[i];
    int lane = t & 31, w = t >> 5;
    int v = s;
    for (int o = 1; o < 32; o <<= 1) {
        int u = __shfl_up_sync(0xffffffffu, v, o);
        if (lane >= o) v += u;
    }
    if (lane == 31) wsum[w] = v;
    __syncthreads();
    if (w == 0) {
        int vv = wsum[lane];
        for (int o = 1; o < 32; o <<= 1) {
            int u = __shfl_up_sync(0xffffffffu, vv, o);
            if (lane >= o) vv += u;
        }
        wsum[lane] = vv;
    }
    __syncthreads();
    int base = (w > 0 ? wsum[w - 1] : 0) + (v - s);
    int run = base;
    for (int i = beg; i < end; i++) {
        csr_off[i] = run;
        csr_cur[i] = run;
        run += csr_cnt[i];
    }
}

__global__ void csr_fill_kernel(const int* __restrict__ rcvr, const int* __restrict__ sndr, int E) {
    int e = blockIdx.x * blockDim.x + threadIdx.x;
    if (e < E) {
        int pos = atomicAdd(&csr_cur[rcvr[e]], 1);
        csr_edge[pos] = e;
        csr_sndr_d[pos] = sndr[e];
    }
}

// ---------------- edge MLP ----------------
template<bool L0>
__global__ __launch_bounds__(256, 1) void edge_mlp_tc(
    int w1off, int w2off,
    const int* __restrict__ sndr, const int* __restrict__ rcvr,
    int gp, int zin_p, int zout_p, int E,
    const float* __restrict__ Wni, const float* __restrict__ Wedge) {
    extern __shared__ unsigned short smu[];
    unsigned short* Ah = smu;
    unsigned short* Al = smu + 2 * A_U16;
    unsigned short* Bh = smu + 4 * A_U16;
    unsigned short* Bl = smu + 4 * A_U16 + 2 * B_U16;
    unsigned short* Hh = smu + 4 * A_U16 + 4 * B_U16;
    unsigned short* Hl = Hh + H_U16;
    __shared__ float wext[L0 ? 640 : 1];

    int tid = threadIdx.x;
    int wid = tid >> 5, lane = tid & 31;
    int g = lane >> 2, tg = lane & 3;
    int wm = wid >> 2, wn = wid & 3;
    int row0 = blockIdx.x * 128;

    int r = tid >> 1;
    int kh = (tid & 1) * 16;
    int eix = row0 + r; if (eix >= E) eix = E - 1;
    int sr = sndr[eix], rr = rcvr[eix];

    if (L0) {
        for (int j = tid; j < 384; j += 256) wext[j] = Wni[j];
        if (tid < 256) wext[384 + tid] = Wedge[tid];
        __syncthreads();
    }

    const unsigned short* gh = g_hi[gp];
    const unsigned short* gl = g_lo[gp];
    const unsigned short* zh = z_hi[zin_p];
    const unsigned short* zl = z_lo[zin_p];

    float acc[4][4][4];
#pragma unroll
    for (int a = 0; a < 4; a++)
#pragma unroll
        for (int b = 0; b < 4; b++)
#pragma unroll
            for (int q = 0; q < 4; q++) acc[a][b][q] = 0.f;

    float sdh = 0.f, sds = 0.f, srm = 0.f, rdh = 0.f, rds = 0.f, rrm = 0.f, qt = 0.f, qhv = 0.f;
    if (L0) {
        sdh = dhat_d[sr];  sds = dstar_d[sr];  srm = resm_d[sr];
        rdh = dhat_d[rr];  rds = dstar_d[rr];  rrm = resm_d[rr];
        qt = qtilde_d[eix]; qhv = qhat_d[eix];
    }

    uint4 pa0, pa1, pa2, pa3, pb0, pb1, pb2, pb3;
    auto prefA = [&](int s) {
        int kk = s * 32 + kh;
        if (L0) {
            float v[16];
            if (kk < 128) {
#pragma unroll
                for (int j = 0; j < 16; j++)
                    v[j] = sdh * wext[kk + j] + sds * wext[128 + kk + j] + srm * wext[256 + kk + j];
            } else if (kk < 256) {
                int c = kk - 128;
#pragma unroll
                for (int j = 0; j < 16; j++)
                    v[j] = rdh * wext[c + j] + rds * wext[128 + c + j] + rrm * wext[256 + c + j];
            } else {
                int c = kk - 256;
#pragma unroll
                for (int j = 0; j < 16; j++)
                    v[j] = qt * wext[384 + c + j] + qhv * wext[384 + 128 + c + j];
            }
            splitpack16(v, pa0, pa1, pa2, pa3);
        } else {
            const unsigned short *hs, *ls; size_t base;
            if (kk < 128)      { hs = gh; ls = gl; base = (size_t)sr * ML + kk; }
            else if (kk < 256) { hs = gh; ls = gl; base = (size_t)rr * ML + (kk - 128); }
            else               { hs = zh; ls = zl; base = (size_t)eix * ML + (kk - 256); }
            pa0 = *(const uint4*)(hs + base);
            pa1 = *(const uint4*)(hs + base + 8);
            pa2 = *(const uint4*)(ls + base);
            pa3 = *(const uint4*)(ls + base + 8);
        }
    };
    auto prefB = [&](int s, int woff, int Kd) {
        int kk = s * 32 + kh;
        const unsigned short* p = wt_hi + woff + (size_t)r * Kd + kk;
        const unsigned short* q = wt_lo + woff + (size_t)r * Kd + kk;
        pb0 = *(const uint4*)p;
        pb1 = *(const uint4*)(p + 8);
        pb2 = *(const uint4*)q;
        pb3 = *(const uint4*)(q + 8);
    };
    auto commitA = [&](int b) {
        unsigned short* a = Ah + b * A_U16 + r * PA + kh;
        *(uint4*)a = pa0; *(uint4*)(a + 8) = pa1;
        unsigned short* a2 = Al + b * A_U16 + r * PA + kh;
        *(uint4*)a2 = pa2; *(uint4*)(a2 + 8) = pa3;
    };
    auto commitB = [&](int b) {
        unsigned short* d0 = Bh + b * B_U16 + r * PB + kh;
        *(uint4*)d0 = pb0; *(uint4*)(d0 + 8) = pb1;
        unsigned short* d1 = Bl + b * B_U16 + r * PB + kh;
        *(uint4*)d1 = pb2; *(uint4*)(d1 + 8) = pb3;
    };

    // stage 1: K = 384, 12 slabs, pipelined
    prefA(0); prefB(0, w1off, 384);
    commitA(0); commitB(0);
    __syncthreads();
    for (int s = 0; s < 12; s++) {
        int b = s & 1;
        if (s < 11) { prefA(s + 1); prefB(s + 1, w1off, 384); }
        k16_step(acc, Ah + b * A_U16, Al + b * A_U16, PA, 0,
                 Bh + b * B_U16, Bl + b * B_U16, 0, wm, wn, lane);
        k16_step(acc, Ah + b * A_U16, Al + b * A_U16, PA, 16,
                 Bh + b * B_U16, Bl + b * B_U16, 16, wm, wn, lane);
        if (s < 11) { commitA((s + 1) & 1); commitB((s + 1) & 1); }
        __syncthreads();
    }
    // relu -> H (split bf16), reset acc
#pragma unroll
    for (int mf = 0; mf < 4; mf++) {
        int r0 = wm * 64 + mf * 16 + g;
#pragma unroll
        for (int nf = 0; nf < 4; nf++) {
            int c = wn * 32 + nf * 8 + tg * 2;
            uint32_t hw, lw;
            split2x2(fmaxf(acc[mf][nf][0], 0.f), fmaxf(acc[mf][nf][1], 0.f), hw, lw);
            *(uint32_t*)&Hh[r0 * PH + c] = hw;
            *(uint32_t*)&Hl[r0 * PH + c] = lw;
            split2x2(fmaxf(acc[mf][nf][2], 0.f), fmaxf(acc[mf][nf][3], 0.f), hw, lw);
            *(uint32_t*)&Hh[(r0 + 8) * PH + c] = hw;
            *(uint32_t*)&Hl[(r0 + 8) * PH + c] = lw;
            acc[mf][nf][0] = acc[mf][nf][1] = acc[mf][nf][2] = acc[mf][nf][3] = 0.f;
        }
    }
    // stage 2: K = 128, A = H, B pipelined
    prefB(0, w2off, 128);
    commitB(0);
    __syncthreads();
    for (int s = 0; s < 4; s++) {
        int b = s & 1;
        if (s < 3) prefB(s + 1, w2off, 128);
        k16_step(acc, Hh, Hl, PH, 32 * s,
                 Bh + b * B_U16, Bl + b * B_U16, 0, wm, wn, lane);
        k16_step(acc, Hh, Hl, PH, 32 * s + 16,
                 Bh + b * B_U16, Bl + b * B_U16, 16, wm, wn, lane);
        if (s < 3) commitB((s + 1) & 1);
        __syncthreads();
    }
    unsigned short* zoh = z_hi[zout_p];
    unsigned short* zol = z_lo[zout_p];
#pragma unroll
    for (int mf = 0; mf < 4; mf++) {
        int gr = row0 + wm * 64 + mf * 16 + g;
#pragma unroll
        for (int nf = 0; nf < 4; nf++) {
            int c = wn * 32 + nf * 8 + tg * 2;
            uint32_t hw, lw;
            if (gr < E) {
                split2x2(acc[mf][nf][0], acc[mf][nf][1], hw, lw);
                *(uint32_t*)&zoh[(size_t)gr * ML + c] = hw;
                *(uint32_t*)&zol[(size_t)gr * ML + c] = lw;
            }
            if (gr + 8 < E) {
                split2x2(acc[mf][nf][2], acc[mf][nf][3], hw, lw);
                *(uint32_t*)&zoh[(size_t)(gr + 8) * ML + c] = hw;
                *(uint32_t*)&zol[(size_t)(gr + 8) * ML + c] = lw;
            }
        }
    }
}

// ---------------- node MLP ----------------
template<bool L0>
__global__ __launch_bounds__(256, 1) void node_mlp_tc(
    int w1off, int w2off, int gp_in, int gp_out, int N,
    const float* __restrict__ Wni) {
    extern __shared__ unsigned short smu[];
    unsigned short* Ah = smu;
    unsigned short* Al = smu + 2 * A_U16;
    unsigned short* Bh = smu + 4 * A_U16;
    unsigned short* Bl = smu + 4 * A_U16 + 2 * B_U16;
    unsigned short* Hh = smu + 4 * A_U16 + 4 * B_U16;
    unsigned short* Hl = Hh + H_U16;
    __shared__ float wext[L0 ? 384 : 1];

    int tid = threadIdx.x;
    int wid = tid >> 5, lane = tid & 31;
    int g = lane >> 2, tg = lane & 3;
    int wm = wid >> 2, wn = wid & 3;
    int row0 = blockIdx.x * 128;

    int r = tid >> 1;
    int kh = (tid & 1) * 16;
    int er = row0 + r; if (er >= N) er = N - 1;

    if (L0) {
        for (int j = tid; j < 384; j += 256) wext[j] = Wni[j];
        __syncthreads();
    }

    const unsigned short* gh = g_hi[gp_in];
    const unsigned short* gl = g_lo[gp_in];

    float acc[4][4][4];
#pragma unroll
    for (int a = 0; a < 4; a++)
#pragma unroll
        for (int b = 0; b < 4; b++)
#pragma unroll
            for (int q = 0; q < 4; q++) acc[a][b][q] = 0.f;

    float ndh = 0.f, nds = 0.f, nrm = 0.f;
    if (L0) { ndh = dhat_d[er]; nds = dstar_d[er]; nrm = resm_d[er]; }

    uint4 pa0, pa1, pa2, pa3, pb0, pb1, pb2, pb3;
    auto prefA = [&](int s) {
        int kk = s * 32 + kh;
        if (L0 && kk < 128) {
            float v[16];
#pragma unroll
            for (int j = 0; j < 16; j++)
                v[j] = ndh * wext[kk + j] + nds * wext[128 + kk + j] + nrm * wext[256 + kk + j];
            splitpack16(v, pa0, pa1, pa2, pa3);
        } else {
            const unsigned short *hs, *ls; size_t base;
            if (kk < 128) { hs = gh; ls = gl; base = (size_t)er * ML + kk; }
            else          { hs = agg_hi; ls = agg_lo; base = (size_t)er * ML + (kk - 128); }
            pa0 = *(const uint4*)(hs + base);
            pa1 = *(const uint4*)(hs + base + 8);
            pa2 = *(const uint4*)(ls + base);
            pa3 = *(const uint4*)(ls + base + 8);
        }
    };
    auto prefB = [&](int s, int woff, int Kd) {
        int kk = s * 32 + kh;
        const unsigned short* p = wt_hi + woff + (size_t)r * Kd + kk;
        const unsigned short* q = wt_lo + woff + (size_t)r * Kd + kk;
        pb0 = *(const uint4*)p;
        pb1 = *(const uint4*)(p + 8);
        pb2 = *(const uint4*)q;
        pb3 = *(const uint4*)(q + 8);
    };
    auto commitA = [&](int b) {
        unsigned short* a = Ah + b * A_U16 + r * PA + kh;
        *(uint4*)a = pa0; *(uint4*)(a + 8) = pa1;
        unsigned short* a2 = Al + b * A_U16 + r * PA + kh;
        *(uint4*)a2 = pa2; *(uint4*)(a2 + 8) = pa3;
    };
    auto commitB = [&](int b) {
        unsigned short* d0 = Bh + b * B_U16 + r * PB + kh;
        *(uint4*)d0 = pb0; *(uint4*)(d0 + 8) = pb1;
        unsigned short* d1 = Bl + b * B_U16 + r * PB + kh;
        *(uint4*)d1 = pb2; *(uint4*)(d1 + 8) = pb3;
    };

    // stage 1: K = 256, 8 slabs
    prefA(0); prefB(0, w1off, 256);
    commitA(0); commitB(0);
    __syncthreads();
    for (int s = 0; s < 8; s++) {
        int b = s & 1;
        if (s < 7) { prefA(s + 1); prefB(s + 1, w1off, 256); }
        k16_step(acc, Ah + b * A_U16, Al + b * A_U16, PA, 0,
                 Bh + b * B_U16, Bl + b * B_U16, 0, wm, wn, lane);
        k16_step(acc, Ah + b * A_U16, Al + b * A_U16, PA, 16,
                 Bh + b * B_U16, Bl + b * B_U16, 16, wm, wn, lane);
        if (s < 7) { commitA((s + 1) & 1); commitB((s + 1) & 1); }
        __syncthreads();
    }
#pragma unroll
    for (int mf = 0; mf < 4; mf++) {
        int r0 = wm * 64 + mf * 16 + g;
#pragma unroll
        for (int nf = 0; nf < 4; nf++) {
            int c = wn * 32 + nf * 8 + tg * 2;
            uint32_t hw, lw;
            split2x2(fmaxf(acc[mf][nf][0], 0.f), fmaxf(acc[mf][nf][1], 0.f), hw, lw);
            *(uint32_t*)&Hh[r0 * PH + c] = hw;
            *(uint32_t*)&Hl[r0 * PH + c] = lw;
            split2x2(fmaxf(acc[mf][nf][2], 0.f), fmaxf(acc[mf][nf][3], 0.f), hw, lw);
            *(uint32_t*)&Hh[(r0 + 8) * PH + c] = hw;
            *(uint32_t*)&Hl[(r0 + 8) * PH + c] = lw;
            acc[mf][nf][0] = acc[mf][nf][1] = acc[mf][nf][2] = acc[mf][nf][3] = 0.f;
        }
    }
    // stage 2: K = 128
    prefB(0, w2off, 128);
    commitB(0);
    __syncthreads();
    for (int s = 0; s < 4; s++) {
        int b = s & 1;
        if (s < 3) prefB(s + 1, w2off, 128);
        k16_step(acc, Hh, Hl, PH, 32 * s,
                 Bh + b * B_U16, Bl + b * B_U16, 0, wm, wn, lane);
        k16_step(acc, Hh, Hl, PH, 32 * s + 16,
                 Bh + b * B_U16, Bl + b * B_U16, 16, wm, wn, lane);
        if (s < 3) commitB((s + 1) & 1);
        __syncthreads();
    }
    unsigned short* goh = g_hi[gp_out];
    unsigned short* gol = g_lo[gp_out];
#pragma unroll
    for (int mf = 0; mf < 4; mf++) {
        int gr = row0 + wm * 64 + mf * 16 + g;
#pragma unroll
        for (int nf = 0; nf < 4; nf++) {
            int c = wn * 32 + nf * 8 + tg * 2;
            uint32_t hw, lw;
            if (gr < N) {
                split2x2(acc[mf][nf][0], acc[mf][nf][1], hw, lw);
                *(uint32_t*)&goh[(size_t)gr * ML + c] = hw;
                *(uint32_t*)&gol[(size_t)gr * ML + c] = lw;
            }
            if (gr + 8 < N) {
                split2x2(acc[mf][nf][2], acc[mf][nf][3], hw, lw);
                *(uint32_t*)&goh[(size_t)(gr + 8) * ML + c] = hw;
                *(uint32_t*)&gol[(size_t)(gr + 8) * ML + c] = lw;
            }
        }
    }
}

// ---------------- zbar ----------------
__global__ __launch_bounds__(256, 1) void zbar_tc(
    const float* __restrict__ Wf,
    const int* __restrict__ sndr, const int* __restrict__ rcvr,
    int gp, int zp, int E, int Eh) {
    extern __shared__ unsigned short smu[];
    unsigned short* Ah = smu;
    unsigned short* Al = smu + 2 * A_U16;
    unsigned short* Bh = smu + 4 * A_U16;
    unsigned short* Bl = smu + 4 * A_U16 + 2 * B_U16;
    __shared__ float wfs[256];
    __shared__ float rowsum[128];

    int tid = threadIdx.x;
    int wid = tid >> 5, lane = tid & 31;
    int g = lane >> 2, tg = lane & 3;
    int wm = wid >> 2, wn = wid & 3;
    int row0 = blockIdx.x * 128;

    int r = tid >> 1;
    int kh = (tid & 1) * 16;
    int eix = row0 + r; if (eix >= E) eix = E - 1;
    int sr = sndr[eix], rr = rcvr[eix];

    wfs[tid] = Wf[tid];
    if (tid < 128) rowsum[tid] = 0.f;
    __syncthreads();

    const unsigned short* gh = g_hi[gp];
    const unsigned short* gl = g_lo[gp];
    const unsigned short* zh = z_hi[zp];
    const unsigned short* zl = z_lo[zp];

    float acc[4][4][4];
#pragma unroll
    for (int a = 0; a < 4; a++)
#pragma unroll
        for (int b = 0; b < 4; b++)
#pragma unroll
            for (int q = 0; q < 4; q++) acc[a][b][q] = 0.f;

    uint4 pa0, pa1, pa2, pa3, pb0, pb1, pb2, pb3;
    auto prefA = [&](int s) {
        int kk = s * 32 + kh;
        const unsigned short *hs, *ls; size_t base;
        if (kk < 128)      { hs = gh; ls = gl; base = (size_t)sr * ML + kk; }
        else if (kk < 256) { hs = gh; ls = gl; base = (size_t)rr * ML + (kk - 128); }
        else               { hs = zh; ls = zl; base = (size_t)eix * ML + (kk - 256); }
        pa0 = *(const uint4*)(hs + base);
        pa1 = *(const uint4*)(hs + base + 8);
        pa2 = *(const uint4*)(ls + base);
        pa3 = *(const uint4*)(ls + base + 8);
    };
    auto prefB = [&](int s) {
        int kk = s * 32 + kh;
        const unsigned short* p = wt_hi + OFF_Z + (size_t)r * 384 + kk;
        const unsigned short* q = wt_lo + OFF_Z + (size_t)r * 384 + kk;
        pb0 = *(const uint4*)p;
        pb1 = *(const uint4*)(p + 8);
        pb2 = *(const uint4*)q;
        pb3 = *(const uint4*)(q + 8);
    };
    auto commitA = [&](int b) {
        unsigned short* a = Ah + b * A_U16 + r * PA + kh;
        *(uint4*)a = pa0; *(uint4*)(a + 8) = pa1;
        unsigned short* a2 = Al + b * A_U16 + r * PA + kh;
        *(uint4*)a2 = pa2; *(uint4*)(a2 + 8) = pa3;
    };
    auto commitB = [&](int b) {
        unsigned short* d0 = Bh + b * B_U16 + r * PB + kh;
        *(uint4*)d0 = pb0; *(uint4*)(d0 + 8) = pb1;
        unsigned short* d1 = Bl + b * B_U16 + r * PB + kh;
        *(uint4*)d1 = pb2; *(uint4*)(d1 + 8) = pb3;
    };

    prefA(0); prefB(0);
    commitA(0); commitB(0);
    __syncthreads();
    for (int s = 0; s < 12; s++) {
        int b = s & 1;
        if (s < 11) { prefA(s + 1); prefB(s + 1); }
        k16_step(acc, Ah + b * A_U16, Al + b * A_U16, PA, 0,
                 Bh + b * B_U16, Bl + b * B_U16, 0, wm, wn, lane);
        k16_step(acc, Ah + b * A_U16, Al + b * A_U16, PA, 16,
                 Bh + b * B_U16, Bl + b * B_U16, 16, wm, wn, lane);
        if (s < 11) { commitA((s + 1) & 1); commitB((s + 1) & 1); }
        __syncthreads();
    }

    float prt[4][2];
#pragma unroll
    for (int mf = 0; mf < 4; mf++) { prt[mf][0] = 0.f; prt[mf][1] = 0.f; }
#pragma unroll
    for (int mf = 0; mf < 4; mf++) {
        int gr0 = row0 + wm * 64 + mf * 16 + g;
        int gr1 = gr0 + 8;
        int off0 = (gr0 < Eh) ? 0 : 128;
        int off1 = (gr1 < Eh) ? 0 : 128;
#pragma unroll
        for (int nf = 0; nf < 4; nf++) {
            int c = wn * 32 + nf * 8 + tg * 2;
            prt[mf][0] += acc[mf][nf][0] * wfs[off0 + c] + acc[mf][nf][1] * wfs[off0 + c + 1];
            prt[mf][1] += acc[mf][nf][2] * wfs[off1 + c] + acc[mf][nf][3] * wfs[off1 + c + 1];
        }
    }
#pragma unroll
    for (int o = 1; o <= 2; o <<= 1)
#pragma unroll
        for (int mf = 0; mf < 4; mf++) {
            prt[mf][0] += __shfl_xor_sync(0xffffffffu, prt[mf][0], o);
            prt[mf][1] += __shfl_xor_sync(0xffffffffu, prt[mf][1], o);
        }
    __syncthreads();
    if (tg == 0) {
#pragma unroll
        for (int mf = 0; mf < 4; mf++) {
            atomicAdd(&rowsum[wm * 64 + mf * 16 + g], prt[mf][0]);
            atomicAdd(&rowsum[wm * 64 + mf * 16 + g + 8], prt[mf][1]);
        }
    }
    __syncthreads();
    if (tid < 128 && row0 + tid < E) dot_buf[row0 + tid] = rowsum[tid];
}

// ---------------- agg (segment max over split z, split output) ----------------
__global__ void agg_kernel(int zp, int N) {
    int t = blockIdx.x * blockDim.x + threadIdx.x;
    if (t >= N * 32) return;
    int n = t >> 5, c4 = (t & 31) * 4;
    const unsigned short* zh = z_hi[zp];
    const unsigned short* zl = z_lo[zp];
    int off = csr_off[n], cnt = csr_cnt[n];
    float m0 = -3.0e38f, m1 = -3.0e38f, m2 = -3.0e38f, m3 = -3.0e38f;
    for (int i = 0; i < cnt; i++) {
        size_t b = (size_t)csr_edge[off + i] * ML + c4;
        uint2 vh = *(const uint2*)&zh[b];
        uint2 vl = *(const uint2*)&zl[b];
        m0 = fmaxf(m0, __uint_as_float(vh.x << 16) + __uint_as_float(vl.x << 16));
        m1 = fmaxf(m1, __uint_as_float(vh.x & 0xffff0000u) + __uint_as_float(vl.x & 0xffff0000u));
        m2 = fmaxf(m2, __uint_as_float(vh.y << 16) + __uint_as_float(vl.y << 16));
        m3 = fmaxf(m3, __uint_as_float(vh.y & 0xffff0000u) + __uint_as_float(vl.y & 0xffff0000u));
    }
    if (cnt == 0) { m0 = m1 = m2 = m3 = 0.f; }
    uint32_t h0, l0, h1, l1;
    split2x2(m0, m1, h0, l0);
    split2x2(m2, m3, h1, l1);
    *(uint2*)&agg_hi[(size_t)n * ML + c4] = make_uint2(h0, h1);
    *(uint2*)&agg_lo[(size_t)n * ML + c4] = make_uint2(l0, l1);
}

// ---------------- fused heads (persistent grid) ----------------
#define HP_BLOCKS 148

__device__ __forceinline__ void gbar() {
    __syncthreads();
    if (threadIdx.x == 0) {
        unsigned int e = *(volatile unsigned int*)&bar_epoch;
        __threadfence();
        unsigned int a = atomicAdd(&bar_cnt, 1u);
        if (a == gridDim.x - 1) {
            bar_cnt = 0;
            __threadfence();
            atomicAdd(&bar_epoch, 1u);
        } else {
            while (*(volatile unsigned int*)&bar_epoch == e) { }
        }
    }
    __syncthreads();
}

__global__ __launch_bounds__(256) void heads_fused(
    const int* __restrict__ sndr, const int* __restrict__ rcvr,
    int N, int E, int Eh, int do_tail, float* __restrict__ out) {
    int gtid = blockIdx.x * blockDim.x + threadIdx.x;
    int gsz = gridDim.x * blockDim.x;
    int nres = *(volatile int*)&nres_d;

    // phase A: q_hat_dir update from dot_buf + pump clamps; head init
    for (int i = gtid; i < Eh; i += gsz) {
        float qd = qhatdir_d[i] + dot_buf[i] + dot_buf[i + Eh];
        float pd = pump_d[Eh + i];
        if (pd == 1.0f) qd = fminf(qd, 0.f);
        if (pd == 2.0f) qd = 0.f;
        qhatdir_d[i] = qd;
        qhat_d[i] = qd;
        qhat_d[i + Eh] = -qd;
    }
    for (int n = gtid; n < N; n += gsz)
        hbuf[0][n] = (resm_d[n] > 0.5f) ? hstar_d[n] : -1.0e30f;
    if (gtid == 0) known_cum = 0;
    gbar();

    // phase B: edge losses in CSR order
    for (int p = gtid; p < E; p += gsz) {
        int e = csr_edge[p];
        float q = __ldcg(&qhat_d[e]);
        float q2 = q * q + 1e-24f;
        float lp = r_d[e] * q * __powf(q2, 0.426f);
        float lpu = -(c0_d[e] - c1_d[e] * __powf(q2, c2_d[e] * 0.5f));
        csr_loss_d[p] = (pump_d[e] != 0.f) ? lpu : lp;
    }
    gbar();

    int off = 0, cnt = 0;
    if (gtid < N) { off = csr_off[gtid]; cnt = csr_cnt[gtid]; }
    int prev = 0;
    int p = 0;
    int stable = 0;
    for (int t = 0; t < 20; t++) {
        if (gtid < N) {
            float hv = hbuf[p][gtid];
            if (hv > -5.0e8f) {
                if (stable == 0) { hbuf[1 - p][gtid] = hv; stable = 1; }
            } else {
                float m = -3.0e38f;
                for (int i = off; i < off + cnt; i++) {
                    float hs = __ldcg(&hbuf[p][csr_sndr_d[i]]);
                    m = fmaxf(m, hs - csr_loss_d[i]);
                }
                if (m > -5.0e8f) {
                    hbuf[1 - p][gtid] = m;
                    atomicAdd(&known_cum, 1);
                } else {
                    hbuf[1 - p][gtid] = hv;
                }
            }
        }
        p = 1 - p;
        gbar();
        int c = *(volatile int*)&known_cum;
        if (c == prev) break;           // no-change round: converged
        prev = c;
        if (c + nres >= N) break;       // everything known: remaining rounds are no-ops
    }
    if (!do_tail) {
        for (int n = gtid; n < N; n += gsz) {
            float hv = hbuf[p][n];
            out[n] = (hv > -5.0e8f) ? hv : 0.f;
        }
        return;
    }
    // tail: q_tilde from heads (normalize inline), pump overrides into q_hat
    for (int e = gtid; e < E; e += gsz) {
        float hs = __ldcg(&hbuf[p][sndr[e]]);
        hs = (hs > -5.0e8f) ? hs : 0.f;
        float hr = __ldcg(&hbuf[p][rcvr[e]]);
        hr = (hr > -5.0e8f) ? hr : 0.f;
        float dh = hs - hr;
        float q = dh * __powf(dh * dh + 1e-24f, -0.23f) / __powf(r_d[e], 0.54f);
        float pe = pump_d[e];
        if (pe != 0.f) q = 0.f;
        qtilde_d[e] = q;
        if (fabsf(pe) == 1.0f) qhat_d[e] = q;
    }
    gbar();
    // d_hat = segment_sum(q_hat)
    for (int n = gtid; n < N; n += gsz) {
        int o = csr_off[n], c2 = csr_cnt[n];
        float s = 0.f;
        for (int i = 0; i < c2; i++) s += __ldcg(&qhat_d[csr_edge[o + i]]);
        dhat_d[n] = s;
    }
}

// ---------------- launch ----------------
extern "C" void kernel_launch(void* const* d_in, const int* in_sizes, int n_in,
                              void* d_out, int out_size) {
    const float* x     = (const float*)d_in[0];
    const float* ea    = (const float*)d_in[1];
    const float* Wni   = (const float*)d_in[2];
    const float* Wedge = (const float*)d_in[3];
    const float* Wz    = (const float*)d_in[4];
    const float* Wf    = (const float*)d_in[5];
    const float* We1   = (const float*)d_in[6];
    const float* We2   = (const float*)d_in[7];
    const float* Wn1   = (const float*)d_in[8];
    const float* Wn2   = (const float*)d_in[9];
    const int*   ei    = (const int*)d_in[10];

    int N  = in_sizes[0] / 5;
    int E  = in_sizes[10] / 2;
    int Eh = E / 2;
    const int* sndr = ei;
    const int* rcvr = ei + E;
    const int K = 3;  // r_iter=1 + n_iter=2 (fixed by dataset)
    const int TB = 256;
    int mNE = N > E ? N : E;

    cudaFuncSetAttribute(edge_mlp_tc<true>,  cudaFuncAttributeMaxDynamicSharedMemorySize, SMEM_MLP);
    cudaFuncSetAttribute(edge_mlp_tc<false>, cudaFuncAttributeMaxDynamicSharedMemorySize, SMEM_MLP);
    cudaFuncSetAttribute(node_mlp_tc<true>,  cudaFuncAttributeMaxDynamicSharedMemorySize, SMEM_MLP);
    cudaFuncSetAttribute(node_mlp_tc<false>, cudaFuncAttributeMaxDynamicSharedMemorySize, SMEM_MLP);
    cudaFuncSetAttribute(zbar_tc,            cudaFuncAttributeMaxDynamicSharedMemorySize, SMEM_ZB);

    pack_kernel<<<(mNE + TB - 1) / TB, TB>>>(x, ea, N, E, Eh);
    csr_count_kernel<<<(E + TB - 1) / TB, TB>>>(rcvr, E, N);
    csr_scan_kernel<<<1, 1024>>>(N);
    csr_fill_kernel<<<(E + TB - 1) / TB, TB>>>(rcvr, sndr, E);
    wprep_all<<<(WT_TOTAL + TB - 1) / TB, TB>>>(We1, We2, Wn1, Wn2, Wz);

    int gE = (E + 127) / 128;
    int gN = (N + 127) / 128;
    const int we1off[2] = {OFF_E1_0, OFF_E1_1};
    const int we2off[2] = {OFF_E2_0, OFF_E2_1};
    const int wn1off[2] = {OFF_N1_0, OFF_N1_1};
    const int wn2off[2] = {OFF_N2_0, OFF_N2_1};

    for (int k = 0; k < K; k++) {
        int gp = 0, zp = 0;
        for (int i = 0; i < 2; i++) {
            if (i == 0)
                edge_mlp_tc<true><<<gE, 256, SMEM_MLP>>>(we1off[i], we2off[i],
                                                         sndr, rcvr, gp, zp, 1 - zp, E, Wni, Wedge);
            else
                edge_mlp_tc<false><<<gE, 256, SMEM_MLP>>>(we1off[i], we2off[i],
                                                          sndr, rcvr, gp, zp, 1 - zp, E, Wni, Wedge);
            agg_kernel<<<(N * 32 + TB - 1) / TB, TB>>>(1 - zp, N);
            if (i == 0)
                node_mlp_tc<true><<<gN, 256, SMEM_MLP>>>(wn1off[i], wn2off[i], gp, 1 - gp, N, Wni);
            else
                node_mlp_tc<false><<<gN, 256, SMEM_MLP>>>(wn1off[i], wn2off[i], gp, 1 - gp, N, Wni);
            gp = 1 - gp;
            zp = 1 - zp;
        }
        zbar_tc<<<gE, 256, SMEM_ZB>>>(Wf, sndr, rcvr, gp, zp, E, Eh);
        heads_fused<<<HP_BLOCKS, 256>>>(sndr, rcvr, N, E, Eh, (k < K - 1) ? 1 : 0, (float*)d_out);
    }
}

// round 15
// speedup vs baseline: 1.2546x; 1.1584x over previous
#include <cuda_runtime.h>
#include <cuda_bf16.h>
#include <math.h>
#include <stdint.h>

#define NMAX 20000
#define EMAX 60000
#define EHMAX 30000
#define ML 128

// ---------------- scratch (static __device__ — no runtime alloc) ----------------
__device__ unsigned short g_hi[2][NMAX * ML], g_lo[2][NMAX * ML];
__device__ unsigned short z_hi[2][EMAX * ML], z_lo[2][EMAX * ML];
__device__ unsigned short agg_hi[NMAX * ML], agg_lo[NMAX * ML];
__device__ float dot_buf[EMAX];
__device__ float qhat_d[EMAX];
__device__ float qtilde_d[EMAX];
__device__ float qhatdir_d[EHMAX];
__device__ float dhat_d[NMAX];
__device__ float hbuf[2][NMAX];
__device__ float r_d[EMAX], pump_d[EMAX], c0_d[EMAX], c1_d[EMAX], c2_d[EMAX];
__device__ float hstar_d[NMAX], dstar_d[NMAX], resm_d[NMAX];
__device__ int   csr_off[NMAX], csr_cnt[NMAX], csr_cur[NMAX], csr_edge[EMAX];
__device__ int   csr_sndr_d[EMAX];
__device__ float csr_loss_d[EMAX];
__device__ int   known_cum;
__device__ int   nres_d;
__device__ unsigned int bar_cnt, bar_epoch;

// folded L0 weights (fp32)
__device__ float w1eff_e[8 * 128];   // [k][c]: x8 -> hidden for edge L0 stage 1
__device__ float wn1eff[3 * 128];    // [k][c]: x3 -> hidden for node L0 stage 1 (g half)

// transposed + split weights: [n][k] layout, bf16 hi / lo
#define WT_TOTAL 278528
__device__ unsigned short wt_hi[WT_TOTAL];
__device__ unsigned short wt_lo[WT_TOTAL];
#define OFF_E1_0 0
#define OFF_E1_1 49152
#define OFF_E2_0 98304
#define OFF_E2_1 114688
#define OFF_N1_0 131072
#define OFF_N1_1 163840
#define OFF_N2_0 196608
#define OFF_N2_1 212992
#define OFF_Z    229376

// ---------------- bf16 split helpers ----------------
__device__ __forceinline__ void split2(float v, unsigned short& h, unsigned short& l) {
    __nv_bfloat16 bh = __float2bfloat16_rn(v);
    h = __bfloat16_as_ushort(bh);
    float resid = v - __bfloat162float(bh);
    l = __bfloat16_as_ushort(__float2bfloat16_rn(resid));
}
__device__ __forceinline__ uint32_t bf16x2_pack(float hi, float lo) {
    uint32_t r;
    asm("cvt.rn.bf16x2.f32 %0, %1, %2;" : "=r"(r) : "f"(hi), "f"(lo));
    return r;
}
__device__ __forceinline__ void split2x2(float v0, float v1, uint32_t& hw, uint32_t& lw) {
    hw = bf16x2_pack(v1, v0);
    float h0 = __uint_as_float(hw << 16);
    float h1 = __uint_as_float(hw & 0xffff0000u);
    lw = bf16x2_pack(v1 - h1, v0 - h0);
}

__device__ __forceinline__ void mma_bf16(float c[4], const uint32_t a[4], const uint32_t b[2]) {
    asm volatile(
        "mma.sync.aligned.m16n8k16.row.col.f32.bf16.bf16.f32 "
        "{%0,%1,%2,%3}, {%4,%5,%6,%7}, {%8,%9}, {%0,%1,%2,%3};\n"
        : "+f"(c[0]), "+f"(c[1]), "+f"(c[2]), "+f"(c[3])
        : "r"(a[0]), "r"(a[1]), "r"(a[2]), "r"(a[3]), "r"(b[0]), "r"(b[1]));
}

__device__ __forceinline__ void ldsm4(uint32_t* r, const unsigned short* p) {
    uint32_t a = (uint32_t)__cvta_generic_to_shared(p);
    asm volatile("ldmatrix.sync.aligned.m8n8.x4.shared.b16 {%0,%1,%2,%3}, [%4];"
                 : "=r"(r[0]), "=r"(r[1]), "=r"(r[2]), "=r"(r[3]) : "r"(a));
}

// ---- smem geometry ----
#define PA 40
#define PB 40
#define PH 136
#define A_U16 (128 * PA)
#define B_U16 (128 * PB)
#define H_U16 (128 * PH)
#define SMEM_MLP  ((4 * A_U16 + 4 * B_U16 + 2 * H_U16) * 2)
#define SMEM_ZB   ((4 * A_U16 + 4 * B_U16) * 2)

// one k16 step of split-bf16 mma using ldmatrix.x4 fragment loads
__device__ __forceinline__ void k16_step(
    float acc[4][4][4],
    const unsigned short* __restrict__ Ah_, const unsigned short* __restrict__ Al_,
    int pa, int ka,
    const unsigned short* __restrict__ Bh_, const unsigned short* __restrict__ Bl_,
    int kb, int wm, int wn, int lane)
{
    int l7 = lane & 7, lb3 = (lane >> 3) & 1, lb4 = lane >> 4;
    uint32_t ah[4][4], al[4][4], bh[4][2], bl[4][2];
    int arow = wm * 64 + l7 + lb3 * 8;
    int akof = ka + lb4 * 8;
#pragma unroll
    for (int mf = 0; mf < 4; mf++) {
        ldsm4(ah[mf], Ah_ + (arow + mf * 16) * pa + akof);
        ldsm4(al[mf], Al_ + (arow + mf * 16) * pa + akof);
    }
    int brow = wn * 32 + l7 + lb4 * 8;
    int bkof = kb + lb3 * 8;
#pragma unroll
    for (int h = 0; h < 2; h++) {
        uint32_t t[4];
        ldsm4(t, Bh_ + (brow + h * 16) * PB + bkof);
        bh[2 * h][0] = t[0]; bh[2 * h][1] = t[1];
        bh[2 * h + 1][0] = t[2]; bh[2 * h + 1][1] = t[3];
        ldsm4(t, Bl_ + (brow + h * 16) * PB + bkof);
        bl[2 * h][0] = t[0]; bl[2 * h][1] = t[1];
        bl[2 * h + 1][0] = t[2]; bl[2 * h + 1][1] = t[3];
    }
#pragma unroll
    for (int mf = 0; mf < 4; mf++)
#pragma unroll
        for (int nf = 0; nf < 4; nf++) {
            mma_bf16(acc[mf][nf], al[mf], bh[nf]);
            mma_bf16(acc[mf][nf], ah[mf], bl[nf]);
            mma_bf16(acc[mf][nf], ah[mf], bh[nf]);
        }
}

// ---------------- weight prep ----------------
__global__ void wprep_all(const float* __restrict__ We1, const float* __restrict__ We2,
                          const float* __restrict__ Wn1, const float* __restrict__ Wn2,
                          const float* __restrict__ Wz) {
    int i = blockIdx.x * blockDim.x + threadIdx.x;
    if (i >= WT_TOTAL) return;
    const float* W; int Kd, off, li;
    if (i < 98304)       { li = i;          W = We1; Kd = 384; off = OFF_E1_0;
                           if (li >= 49152) { W = We1 + 49152; off = OFF_E1_1; li -= 49152; } }
    else if (i < 131072) { li = i - 98304;  W = We2; Kd = 128; off = OFF_E2_0;
                           if (li >= 16384) { W = We2 + 16384; off = OFF_E2_1; li -= 16384; } }
    else if (i < 196608) { li = i - 131072; W = Wn1; Kd = 256; off = OFF_N1_0;
                           if (li >= 32768) { W = Wn1 + 32768; off = OFF_N1_1; li -= 32768; } }
    else if (i < 229376) { li = i - 196608; W = Wn2; Kd = 128; off = OFF_N2_0;
                           if (li >= 16384) { W = Wn2 + 16384; off = OFF_N2_1; li -= 16384; } }
    else                 { li = i - 229376; W = Wz;  Kd = 384; off = OFF_Z; }
    int k = li >> 7, n = li & 127;
    unsigned short h, l;
    split2(W[li], h, l);
    wt_hi[off + (size_t)n * Kd + k] = h;
    wt_lo[off + (size_t)n * Kd + k] = l;
}

// fold low-rank L0 inputs through layer-0 W1 matrices (fp32)
__global__ void wcomb_kernel(const float* __restrict__ We1, const float* __restrict__ Wedge,
                             const float* __restrict__ Wni, const float* __restrict__ Wn1) {
    int i = blockIdx.x * blockDim.x + threadIdx.x;
    if (i < 1024) {
        int k = i >> 7, c = i & 127;
        float s = 0.f;
        if (k < 3) {
            for (int j = 0; j < 128; j++) s += Wni[k * 128 + j] * We1[j * 128 + c];
        } else if (k < 6) {
            int kk = k - 3;
            for (int j = 0; j < 128; j++) s += Wni[kk * 128 + j] * We1[(128 + j) * 128 + c];
        } else {
            int kk = k - 6;
            for (int j = 0; j < 128; j++) s += Wedge[kk * 128 + j] * We1[(256 + j) * 128 + c];
        }
        w1eff_e[i] = s;
    } else if (i < 1024 + 384) {
        int ii = i - 1024;
        int k = ii >> 7, c = ii & 127;
        float s = 0.f;
        for (int j = 0; j < 128; j++) s += Wni[k * 128 + j] * Wn1[j * 128 + c];
        wn1eff[ii] = s;
    }
}

// ---------------- setup kernels ----------------
__global__ void pack_kernel(const float* __restrict__ x, const float* __restrict__ ea,
                            int N, int E, int Eh) {
    int i = blockIdx.x * blockDim.x + threadIdx.x;
    if (i == 0) nres_d = 0;
    if (i < E) {
        r_d[i]    = ea[i * 8 + 0];
        pump_d[i] = ea[i * 8 + 3];
        c0_d[i]   = ea[i * 8 + 4];
        c1_d[i]   = ea[i * 8 + 5];
        c2_d[i]   = ea[i * 8 + 6];
        qhat_d[i] = 0.f;
        qtilde_d[i] = 0.f;
        if (i < Eh) qhatdir_d[i] = 0.f;
    }
    if (i < N) {
        hstar_d[i] = x[i * 5 + 0];
        dstar_d[i] = x[i * 5 + 1];
        resm_d[i]  = x[i * 5 + 4];
        dhat_d[i]  = 0.f;
        csr_cnt[i] = 0;
    }
}

__global__ void csr_count_kernel(const int* __restrict__ rcvr, int E, int N) {
    int e = blockIdx.x * blockDim.x + threadIdx.x;
    if (e < E) atomicAdd(&csr_cnt[rcvr[e]], 1);
    if (e < N && resm_d[e] > 0.5f) atomicAdd(&nres_d, 1);
}

__global__ void csr_scan_kernel(int N) {
    __shared__ int wsum[32];
    int t = threadIdx.x;
    int C = (N + 1023) >> 10;
    int beg = t * C;
    int end = beg + C; if (end > N) end = N;
    int s = 0;
    for (int i = beg; i < end; i++) s += csr_cnt[i];
    int lane = t & 31, w = t >> 5;
    int v = s;
    for (int o = 1; o < 32; o <<= 1) {
        int u = __shfl_up_sync(0xffffffffu, v, o);
        if (lane >= o) v += u;
    }
    if (lane == 31) wsum[w] = v;
    __syncthreads();
    if (w == 0) {
        int vv = wsum[lane];
        for (int o = 1; o < 32; o <<= 1) {
            int u = __shfl_up_sync(0xffffffffu, vv, o);
            if (lane >= o) vv += u;
        }
        wsum[lane] = vv;
    }
    __syncthreads();
    int base = (w > 0 ? wsum[w - 1] : 0) + (v - s);
    int run = base;
    for (int i = beg; i < end; i++) {
        csr_off[i] = run;
        csr_cur[i] = run;
        run += csr_cnt[i];
    }
}

__global__ void csr_fill_kernel(const int* __restrict__ rcvr, const int* __restrict__ sndr, int E) {
    int e = blockIdx.x * blockDim.x + threadIdx.x;
    if (e < E) {
        int pos = atomicAdd(&csr_cur[rcvr[e]], 1);
        csr_edge[pos] = e;
        csr_sndr_d[pos] = sndr[e];
    }
}

// ---------------- edge MLP ----------------
template<bool L0>
__global__ __launch_bounds__(256, 1) void edge_mlp_tc(
    int w1off, int w2off,
    const int* __restrict__ sndr, const int* __restrict__ rcvr,
    int gp, int zin_p, int zout_p, int E) {
    extern __shared__ unsigned short smu[];
    unsigned short* Ah = smu;
    unsigned short* Al = smu + 2 * A_U16;
    unsigned short* Bh = smu + 4 * A_U16;
    unsigned short* Bl = smu + 4 * A_U16 + 2 * B_U16;
    unsigned short* Hh = smu + 4 * A_U16 + 4 * B_U16;
    unsigned short* Hl = Hh + H_U16;
    __shared__ float lsm[L0 ? 2048 : 1];   // w1e[1024] + x8s[128*8]

    int tid = threadIdx.x;
    int wid = tid >> 5, lane = tid & 31;
    int g = lane >> 2, tg = lane & 3;
    int wm = wid >> 2, wn = wid & 3;
    int row0 = blockIdx.x * 128;

    int r = tid >> 1;
    int kh = (tid & 1) * 16;
    int eix = row0 + r; if (eix >= E) eix = E - 1;
    int sr = sndr[eix], rr = rcvr[eix];

    const unsigned short* gh = g_hi[gp];
    const unsigned short* gl = g_lo[gp];
    const unsigned short* zh = z_hi[zin_p];
    const unsigned short* zl = z_lo[zin_p];

    float acc[4][4][4];
#pragma unroll
    for (int a = 0; a < 4; a++)
#pragma unroll
        for (int b = 0; b < 4; b++)
#pragma unroll
            for (int q = 0; q < 4; q++) acc[a][b][q] = 0.f;

    uint4 pa0, pa1, pa2, pa3, pb0, pb1, pb2, pb3;
    auto prefA = [&](int s) {
        int kk = s * 32 + kh;
        const unsigned short *hs, *ls; size_t base;
        if (kk < 128)      { hs = gh; ls = gl; base = (size_t)sr * ML + kk; }
        else if (kk < 256) { hs = gh; ls = gl; base = (size_t)rr * ML + (kk - 128); }
        else               { hs = zh; ls = zl; base = (size_t)eix * ML + (kk - 256); }
        pa0 = *(const uint4*)(hs + base);
        pa1 = *(const uint4*)(hs + base + 8);
        pa2 = *(const uint4*)(ls + base);
        pa3 = *(const uint4*)(ls + base + 8);
    };
    auto prefB = [&](int s, int woff, int Kd) {
        int kk = s * 32 + kh;
        const unsigned short* p = wt_hi + woff + (size_t)r * Kd + kk;
        const unsigned short* q = wt_lo + woff + (size_t)r * Kd + kk;
        pb0 = *(const uint4*)p;
        pb1 = *(const uint4*)(p + 8);
        pb2 = *(const uint4*)q;
        pb3 = *(const uint4*)(q + 8);
    };
    auto commitA = [&](int b) {
        unsigned short* a = Ah + b * A_U16 + r * PA + kh;
        *(uint4*)a = pa0; *(uint4*)(a + 8) = pa1;
        unsigned short* a2 = Al + b * A_U16 + r * PA + kh;
        *(uint4*)a2 = pa2; *(uint4*)(a2 + 8) = pa3;
    };
    auto commitB = [&](int b) {
        unsigned short* d0 = Bh + b * B_U16 + r * PB + kh;
        *(uint4*)d0 = pb0; *(uint4*)(d0 + 8) = pb1;
        unsigned short* d1 = Bl + b * B_U16 + r * PB + kh;
        *(uint4*)d1 = pb2; *(uint4*)(d1 + 8) = pb3;
    };

    if (L0) {
        // stage 1 (folded, fp32): acc = x8 @ w1eff_e, K = 8
        float* w1e = lsm;
        float* x8s = lsm + 1024;
        for (int j = tid; j < 1024; j += 256) w1e[j] = w1eff_e[j];
        if ((tid & 1) == 0) {
            x8s[r * 8 + 0] = dhat_d[sr];
            x8s[r * 8 + 1] = dstar_d[sr];
            x8s[r * 8 + 2] = resm_d[sr];
            x8s[r * 8 + 3] = dhat_d[rr];
            x8s[r * 8 + 4] = dstar_d[rr];
            x8s[r * 8 + 5] = resm_d[rr];
            x8s[r * 8 + 6] = qtilde_d[eix];
            x8s[r * 8 + 7] = qhat_d[eix];
        }
        __syncthreads();
#pragma unroll
        for (int mf = 0; mf < 4; mf++) {
            int r0 = wm * 64 + mf * 16 + g;
            float xa[8], xb[8];
#pragma unroll
            for (int k = 0; k < 8; k++) { xa[k] = x8s[r0 * 8 + k]; xb[k] = x8s[(r0 + 8) * 8 + k]; }
#pragma unroll
            for (int nf = 0; nf < 4; nf++) {
                int c = wn * 32 + nf * 8 + tg * 2;
                float s00 = 0.f, s01 = 0.f, s10 = 0.f, s11 = 0.f;
#pragma unroll
                for (int k = 0; k < 8; k++) {
                    float w0 = w1e[k * 128 + c], w1 = w1e[k * 128 + c + 1];
                    s00 += xa[k] * w0; s01 += xa[k] * w1;
                    s10 += xb[k] * w0; s11 += xb[k] * w1;
                }
                acc[mf][nf][0] = s00; acc[mf][nf][1] = s01;
                acc[mf][nf][2] = s10; acc[mf][nf][3] = s11;
            }
        }
    } else {
        // stage 1: K = 384, 12 slabs, pipelined
        prefA(0); prefB(0, w1off, 384);
        commitA(0); commitB(0);
        __syncthreads();
        for (int s = 0; s < 12; s++) {
            int b = s & 1;
            if (s < 11) { prefA(s + 1); prefB(s + 1, w1off, 384); }
            k16_step(acc, Ah + b * A_U16, Al + b * A_U16, PA, 0,
                     Bh + b * B_U16, Bl + b * B_U16, 0, wm, wn, lane);
            k16_step(acc, Ah + b * A_U16, Al + b * A_U16, PA, 16,
                     Bh + b * B_U16, Bl + b * B_U16, 16, wm, wn, lane);
            if (s < 11) { commitA((s + 1) & 1); commitB((s + 1) & 1); }
            __syncthreads();
        }
    }
    // relu -> H (split bf16), reset acc
#pragma unroll
    for (int mf = 0; mf < 4; mf++) {
        int r0 = wm * 64 + mf * 16 + g;
#pragma unroll
        for (int nf = 0; nf < 4; nf++) {
            int c = wn * 32 + nf * 8 + tg * 2;
            uint32_t hw, lw;
            split2x2(fmaxf(acc[mf][nf][0], 0.f), fmaxf(acc[mf][nf][1], 0.f), hw, lw);
            *(uint32_t*)&Hh[r0 * PH + c] = hw;
            *(uint32_t*)&Hl[r0 * PH + c] = lw;
            split2x2(fmaxf(acc[mf][nf][2], 0.f), fmaxf(acc[mf][nf][3], 0.f), hw, lw);
            *(uint32_t*)&Hh[(r0 + 8) * PH + c] = hw;
            *(uint32_t*)&Hl[(r0 + 8) * PH + c] = lw;
            acc[mf][nf][0] = acc[mf][nf][1] = acc[mf][nf][2] = acc[mf][nf][3] = 0.f;
        }
    }
    // stage 2: K = 128, A = H, B pipelined
    prefB(0, w2off, 128);
    commitB(0);
    __syncthreads();
    for (int s = 0; s < 4; s++) {
        int b = s & 1;
        if (s < 3) prefB(s + 1, w2off, 128);
        k16_step(acc, Hh, Hl, PH, 32 * s,
                 Bh + b * B_U16, Bl + b * B_U16, 0, wm, wn, lane);
        k16_step(acc, Hh, Hl, PH, 32 * s + 16,
                 Bh + b * B_U16, Bl + b * B_U16, 16, wm, wn, lane);
        if (s < 3) commitB((s + 1) & 1);
        __syncthreads();
    }
    unsigned short* zoh = z_hi[zout_p];
    unsigned short* zol = z_lo[zout_p];
#pragma unroll
    for (int mf = 0; mf < 4; mf++) {
        int gr = row0 + wm * 64 + mf * 16 + g;
#pragma unroll
        for (int nf = 0; nf < 4; nf++) {
            int c = wn * 32 + nf * 8 + tg * 2;
            uint32_t hw, lw;
            if (gr < E) {
                split2x2(acc[mf][nf][0], acc[mf][nf][1], hw, lw);
                *(uint32_t*)&zoh[(size_t)gr * ML + c] = hw;
                *(uint32_t*)&zol[(size_t)gr * ML + c] = lw;
            }
            if (gr + 8 < E) {
                split2x2(acc[mf][nf][2], acc[mf][nf][3], hw, lw);
                *(uint32_t*)&zoh[(size_t)(gr + 8) * ML + c] = hw;
                *(uint32_t*)&zol[(size_t)(gr + 8) * ML + c] = lw;
            }
        }
    }
}

// ---------------- node MLP ----------------
template<bool L0>
__global__ __launch_bounds__(256, 1) void node_mlp_tc(
    int w1off, int w2off, int gp_in, int gp_out, int N) {
    extern __shared__ unsigned short smu[];
    unsigned short* Ah = smu;
    unsigned short* Al = smu + 2 * A_U16;
    unsigned short* Bh = smu + 4 * A_U16;
    unsigned short* Bl = smu + 4 * A_U16 + 2 * B_U16;
    unsigned short* Hh = smu + 4 * A_U16 + 4 * B_U16;
    unsigned short* Hl = Hh + H_U16;
    __shared__ float lsm[L0 ? (384 + 128 * 3) : 1];  // wn1e[384] + x3s[128*3]

    int tid = threadIdx.x;
    int wid = tid >> 5, lane = tid & 31;
    int g = lane >> 2, tg = lane & 3;
    int wm = wid >> 2, wn = wid & 3;
    int row0 = blockIdx.x * 128;

    int r = tid >> 1;
    int kh = (tid & 1) * 16;
    int er = row0 + r; if (er >= N) er = N - 1;

    if (L0) {
        for (int j = tid; j < 384; j += 256) lsm[j] = wn1eff[j];
        if ((tid & 1) == 0) {
            lsm[384 + r * 3 + 0] = dhat_d[er];
            lsm[384 + r * 3 + 1] = dstar_d[er];
            lsm[384 + r * 3 + 2] = resm_d[er];
        }
        __syncthreads();
    }

    const unsigned short* gh = g_hi[gp_in];
    const unsigned short* gl = g_lo[gp_in];

    float acc[4][4][4];
#pragma unroll
    for (int a = 0; a < 4; a++)
#pragma unroll
        for (int b = 0; b < 4; b++)
#pragma unroll
            for (int q = 0; q < 4; q++) acc[a][b][q] = 0.f;

    uint4 pa0, pa1, pa2, pa3, pb0, pb1, pb2, pb3;
    auto prefA = [&](int s) {
        int kk = s * 32 + kh;
        const unsigned short *hs, *ls; size_t base;
        if (kk < 128) { hs = gh; ls = gl; base = (size_t)er * ML + kk; }
        else          { hs = agg_hi; ls = agg_lo; base = (size_t)er * ML + (kk - 128); }
        pa0 = *(const uint4*)(hs + base);
        pa1 = *(const uint4*)(hs + base + 8);
        pa2 = *(const uint4*)(ls + base);
        pa3 = *(const uint4*)(ls + base + 8);
    };
    auto prefB = [&](int s, int woff, int Kd) {
        int kk = s * 32 + kh;
        const unsigned short* p = wt_hi + woff + (size_t)r * Kd + kk;
        const unsigned short* q = wt_lo + woff + (size_t)r * Kd + kk;
        pb0 = *(const uint4*)p;
        pb1 = *(const uint4*)(p + 8);
        pb2 = *(const uint4*)q;
        pb3 = *(const uint4*)(q + 8);
    };
    auto commitA = [&](int b) {
        unsigned short* a = Ah + b * A_U16 + r * PA + kh;
        *(uint4*)a = pa0; *(uint4*)(a + 8) = pa1;
        unsigned short* a2 = Al + b * A_U16 + r * PA + kh;
        *(uint4*)a2 = pa2; *(uint4*)(a2 + 8) = pa3;
    };
    auto commitB = [&](int b) {
        unsigned short* d0 = Bh + b * B_U16 + r * PB + kh;
        *(uint4*)d0 = pb0; *(uint4*)(d0 + 8) = pb1;
        unsigned short* d1 = Bl + b * B_U16 + r * PB + kh;
        *(uint4*)d1 = pb2; *(uint4*)(d1 + 8) = pb3;
    };

    // stage 1: K = 256 (L0: only agg half, s = 4..7)
    const int s0 = L0 ? 4 : 0;
    prefA(s0); prefB(s0, w1off, 256);
    commitA(s0 & 1); commitB(s0 & 1);
    __syncthreads();
    for (int s = s0; s < 8; s++) {
        int b = s & 1;
        if (s < 7) { prefA(s + 1); prefB(s + 1, w1off, 256); }
        k16_step(acc, Ah + b * A_U16, Al + b * A_U16, PA, 0,
                 Bh + b * B_U16, Bl + b * B_U16, 0, wm, wn, lane);
        k16_step(acc, Ah + b * A_U16, Al + b * A_U16, PA, 16,
                 Bh + b * B_U16, Bl + b * B_U16, 16, wm, wn, lane);
        if (s < 7) { commitA((s + 1) & 1); commitB((s + 1) & 1); }
        __syncthreads();
    }
#pragma unroll
    for (int mf = 0; mf < 4; mf++) {
        int r0 = wm * 64 + mf * 16 + g;
#pragma unroll
        for (int nf = 0; nf < 4; nf++) {
            int c = wn * 32 + nf * 8 + tg * 2;
            float v0 = acc[mf][nf][0], v1 = acc[mf][nf][1];
            float v2 = acc[mf][nf][2], v3 = acc[mf][nf][3];
            if (L0) {
                const float* x3a = lsm + 384 + r0 * 3;
                const float* x3b = lsm + 384 + (r0 + 8) * 3;
#pragma unroll
                for (int k = 0; k < 3; k++) {
                    float w0 = lsm[k * 128 + c], w1 = lsm[k * 128 + c + 1];
                    v0 += x3a[k] * w0; v1 += x3a[k] * w1;
                    v2 += x3b[k] * w0; v3 += x3b[k] * w1;
                }
            }
            uint32_t hw, lw;
            split2x2(fmaxf(v0, 0.f), fmaxf(v1, 0.f), hw, lw);
            *(uint32_t*)&Hh[r0 * PH + c] = hw;
            *(uint32_t*)&Hl[r0 * PH + c] = lw;
            split2x2(fmaxf(v2, 0.f), fmaxf(v3, 0.f), hw, lw);
            *(uint32_t*)&Hh[(r0 + 8) * PH + c] = hw;
            *(uint32_t*)&Hl[(r0 + 8) * PH + c] = lw;
            acc[mf][nf][0] = acc[mf][nf][1] = acc[mf][nf][2] = acc[mf][nf][3] = 0.f;
        }
    }
    // stage 2: K = 128
    prefB(0, w2off, 128);
    commitB(0);
    __syncthreads();
    for (int s = 0; s < 4; s++) {
        int b = s & 1;
        if (s < 3) prefB(s + 1, w2off, 128);
        k16_step(acc, Hh, Hl, PH, 32 * s,
                 Bh + b * B_U16, Bl + b * B_U16, 0, wm, wn, lane);
        k16_step(acc, Hh, Hl, PH, 32 * s + 16,
                 Bh + b * B_U16, Bl + b * B_U16, 16, wm, wn, lane);
        if (s < 3) commitB((s + 1) & 1);
        __syncthreads();
    }
    unsigned short* goh = g_hi[gp_out];
    unsigned short* gol = g_lo[gp_out];
#pragma unroll
    for (int mf = 0; mf < 4; mf++) {
        int gr = row0 + wm * 64 + mf * 16 + g;
#pragma unroll
        for (int nf = 0; nf < 4; nf++) {
            int c = wn * 32 + nf * 8 + tg * 2;
            uint32_t hw, lw;
            if (gr < N) {
                split2x2(acc[mf][nf][0], acc[mf][nf][1], hw, lw);
                *(uint32_t*)&goh[(size_t)gr * ML + c] = hw;
                *(uint32_t*)&gol[(size_t)gr * ML + c] = lw;
            }
            if (gr + 8 < N) {
                split2x2(acc[mf][nf][2], acc[mf][nf][3], hw, lw);
                *(uint32_t*)&goh[(size_t)(gr + 8) * ML + c] = hw;
                *(uint32_t*)&gol[(size_t)(gr + 8) * ML + c] = lw;
            }
        }
    }
}

// ---------------- zbar ----------------
__global__ __launch_bounds__(256, 1) void zbar_tc(
    const float* __restrict__ Wf,
    const int* __restrict__ sndr, const int* __restrict__ rcvr,
    int gp, int zp, int E, int Eh) {
    extern __shared__ unsigned short smu[];
    unsigned short* Ah = smu;
    unsigned short* Al = smu + 2 * A_U16;
    unsigned short* Bh = smu + 4 * A_U16;
    unsigned short* Bl = smu + 4 * A_U16 + 2 * B_U16;
    __shared__ float wfs[256];
    __shared__ float rowsum[128];

    int tid = threadIdx.x;
    int wid = tid >> 5, lane = tid & 31;
    int g = lane >> 2, tg = lane & 3;
    int wm = wid >> 2, wn = wid & 3;
    int row0 = blockIdx.x * 128;

    int r = tid >> 1;
    int kh = (tid & 1) * 16;
    int eix = row0 + r; if (eix >= E) eix = E - 1;
    int sr = sndr[eix], rr = rcvr[eix];

    wfs[tid] = Wf[tid];
    if (tid < 128) rowsum[tid] = 0.f;
    __syncthreads();

    const unsigned short* gh = g_hi[gp];
    const unsigned short* gl = g_lo[gp];
    const unsigned short* zh = z_hi[zp];
    const unsigned short* zl = z_lo[zp];

    float acc[4][4][4];
#pragma unroll
    for (int a = 0; a < 4; a++)
#pragma unroll
        for (int b = 0; b < 4; b++)
#pragma unroll
            for (int q = 0; q < 4; q++) acc[a][b][q] = 0.f;

    uint4 pa0, pa1, pa2, pa3, pb0, pb1, pb2, pb3;
    auto prefA = [&](int s) {
        int kk = s * 32 + kh;
        const unsigned short *hs, *ls; size_t base;
        if (kk < 128)      { hs = gh; ls = gl; base = (size_t)sr * ML + kk; }
        else if (kk < 256) { hs = gh; ls = gl; base = (size_t)rr * ML + (kk - 128); }
        else               { hs = zh; ls = zl; base = (size_t)eix * ML + (kk - 256); }
        pa0 = *(const uint4*)(hs + base);
        pa1 = *(const uint4*)(hs + base + 8);
        pa2 = *(const uint4*)(ls + base);
        pa3 = *(const uint4*)(ls + base + 8);
    };
    auto prefB = [&](int s) {
        int kk = s * 32 + kh;
        const unsigned short* p = wt_hi + OFF_Z + (size_t)r * 384 + kk;
        const unsigned short* q = wt_lo + OFF_Z + (size_t)r * 384 + kk;
        pb0 = *(const uint4*)p;
        pb1 = *(const uint4*)(p + 8);
        pb2 = *(const uint4*)q;
        pb3 = *(const uint4*)(q + 8);
    };
    auto commitA = [&](int b) {
        unsigned short* a = Ah + b * A_U16 + r * PA + kh;
        *(uint4*)a = pa0; *(uint4*)(a + 8) = pa1;
        unsigned short* a2 = Al + b * A_U16 + r * PA + kh;
        *(uint4*)a2 = pa2; *(uint4*)(a2 + 8) = pa3;
    };
    auto commitB = [&](int b) {
        unsigned short* d0 = Bh + b * B_U16 + r * PB + kh;
        *(uint4*)d0 = pb0; *(uint4*)(d0 + 8) = pb1;
        unsigned short* d1 = Bl + b * B_U16 + r * PB + kh;
        *(uint4*)d1 = pb2; *(uint4*)(d1 + 8) = pb3;
    };

    prefA(0); prefB(0);
    commitA(0); commitB(0);
    __syncthreads();
    for (int s = 0; s < 12; s++) {
        int b = s & 1;
        if (s < 11) { prefA(s + 1); prefB(s + 1); }
        k16_step(acc, Ah + b * A_U16, Al + b * A_U16, PA, 0,
                 Bh + b * B_U16, Bl + b * B_U16, 0, wm, wn, lane);
        k16_step(acc, Ah + b * A_U16, Al + b * A_U16, PA, 16,
                 Bh + b * B_U16, Bl + b * B_U16, 16, wm, wn, lane);
        if (s < 11) { commitA((s + 1) & 1); commitB((s + 1) & 1); }
        __syncthreads();
    }

    float prt[4][2];
#pragma unroll
    for (int mf = 0; mf < 4; mf++) { prt[mf][0] = 0.f; prt[mf][1] = 0.f; }
#pragma unroll
    for (int mf = 0; mf < 4; mf++) {
        int gr0 = row0 + wm * 64 + mf * 16 + g;
        int gr1 = gr0 + 8;
        int off0 = (gr0 < Eh) ? 0 : 128;
        int off1 = (gr1 < Eh) ? 0 : 128;
#pragma unroll
        for (int nf = 0; nf < 4; nf++) {
            int c = wn * 32 + nf * 8 + tg * 2;
            prt[mf][0] += acc[mf][nf][0] * wfs[off0 + c] + acc[mf][nf][1] * wfs[off0 + c + 1];
            prt[mf][1] += acc[mf][nf][2] * wfs[off1 + c] + acc[mf][nf][3] * wfs[off1 + c + 1];
        }
    }
#pragma unroll
    for (int o = 1; o <= 2; o <<= 1)
#pragma unroll
        for (int mf = 0; mf < 4; mf++) {
            prt[mf][0] += __shfl_xor_sync(0xffffffffu, prt[mf][0], o);
            prt[mf][1] += __shfl_xor_sync(0xffffffffu, prt[mf][1], o);
        }
    __syncthreads();
    if (tg == 0) {
#pragma unroll
        for (int mf = 0; mf < 4; mf++) {
            atomicAdd(&rowsum[wm * 64 + mf * 16 + g], prt[mf][0]);
            atomicAdd(&rowsum[wm * 64 + mf * 16 + g + 8], prt[mf][1]);
        }
    }
    __syncthreads();
    if (tid < 128 && row0 + tid < E) dot_buf[row0 + tid] = rowsum[tid];
}

// ---------------- agg (segment max over split z, split output) ----------------
__global__ void agg_kernel(int zp, int N) {
    int t = blockIdx.x * blockDim.x + threadIdx.x;
    if (t >= N * 32) return;
    int n = t >> 5, c4 = (t & 31) * 4;
    const unsigned short* zh = z_hi[zp];
    const unsigned short* zl = z_lo[zp];
    int off = csr_off[n], cnt = csr_cnt[n];
    float m0 = -3.0e38f, m1 = -3.0e38f, m2 = -3.0e38f, m3 = -3.0e38f;
    for (int i = 0; i < cnt; i++) {
        size_t b = (size_t)csr_edge[off + i] * ML + c4;
        uint2 vh = *(const uint2*)&zh[b];
        uint2 vl = *(const uint2*)&zl[b];
        m0 = fmaxf(m0, __uint_as_float(vh.x << 16) + __uint_as_float(vl.x << 16));
        m1 = fmaxf(m1, __uint_as_float(vh.x & 0xffff0000u) + __uint_as_float(vl.x & 0xffff0000u));
        m2 = fmaxf(m2, __uint_as_float(vh.y << 16) + __uint_as_float(vl.y << 16));
        m3 = fmaxf(m3, __uint_as_float(vh.y & 0xffff0000u) + __uint_as_float(vl.y & 0xffff0000u));
    }
    if (cnt == 0) { m0 = m1 = m2 = m3 = 0.f; }
    uint32_t h0, l0, h1, l1;
    split2x2(m0, m1, h0, l0);
    split2x2(m2, m3, h1, l1);
    *(uint2*)&agg_hi[(size_t)n * ML + c4] = make_uint2(h0, h1);
    *(uint2*)&agg_lo[(size_t)n * ML + c4] = make_uint2(l0, l1);
}

// ---------------- fused heads (persistent grid) ----------------
#define HP_BLOCKS 148

__device__ __forceinline__ void gbar() {
    __syncthreads();
    if (threadIdx.x == 0) {
        unsigned int e = *(volatile unsigned int*)&bar_epoch;
        __threadfence();
        unsigned int a = atomicAdd(&bar_cnt, 1u);
        if (a == gridDim.x - 1) {
            bar_cnt = 0;
            __threadfence();
            atomicAdd(&bar_epoch, 1u);
        } else {
            while (*(volatile unsigned int*)&bar_epoch == e) { }
        }
    }
    __syncthreads();
}

__global__ __launch_bounds__(256) void heads_fused(
    const int* __restrict__ sndr, const int* __restrict__ rcvr,
    int N, int E, int Eh, int do_tail, float* __restrict__ out) {
    int gtid = blockIdx.x * blockDim.x + threadIdx.x;
    int gsz = gridDim.x * blockDim.x;
    int nres = *(volatile int*)&nres_d;

    for (int i = gtid; i < Eh; i += gsz) {
        float qd = qhatdir_d[i] + dot_buf[i] + dot_buf[i + Eh];
        float pd = pump_d[Eh + i];
        if (pd == 1.0f) qd = fminf(qd, 0.f);
        if (pd == 2.0f) qd = 0.f;
        qhatdir_d[i] = qd;
        qhat_d[i] = qd;
        qhat_d[i + Eh] = -qd;
    }
    for (int n = gtid; n < N; n += gsz)
        hbuf[0][n] = (resm_d[n] > 0.5f) ? hstar_d[n] : -1.0e30f;
    if (gtid == 0) known_cum = 0;
    gbar();

    for (int p = gtid; p < E; p += gsz) {
        int e = csr_edge[p];
        float q = __ldcg(&qhat_d[e]);
        float q2 = q * q + 1e-24f;
        float lp = r_d[e] * q * __powf(q2, 0.426f);
        float lpu = -(c0_d[e] - c1_d[e] * __powf(q2, c2_d[e] * 0.5f));
        csr_loss_d[p] = (pump_d[e] != 0.f) ? lpu : lp;
    }
    gbar();

    int off = 0, cnt = 0;
    if (gtid < N) { off = csr_off[gtid]; cnt = csr_cnt[gtid]; }
    int prev = 0;
    int p = 0;
    int stable = 0;
    for (int t = 0; t < 20; t++) {
        if (gtid < N) {
            float hv = hbuf[p][gtid];
            if (hv > -5.0e8f) {
                if (stable == 0) { hbuf[1 - p][gtid] = hv; stable = 1; }
            } else {
                float m = -3.0e38f;
                for (int i = off; i < off + cnt; i++) {
                    float hs = __ldcg(&hbuf[p][csr_sndr_d[i]]);
                    m = fmaxf(m, hs - csr_loss_d[i]);
                }
                if (m > -5.0e8f) {
                    hbuf[1 - p][gtid] = m;
                    atomicAdd(&known_cum, 1);
                } else {
                    hbuf[1 - p][gtid] = hv;
                }
            }
        }
        p = 1 - p;
        gbar();
        int c = *(volatile int*)&known_cum;
        if (c == prev) break;
        prev = c;
        if (c + nres >= N) break;
    }
    if (!do_tail) {
        for (int n = gtid; n < N; n += gsz) {
            float hv = hbuf[p][n];
            out[n] = (hv > -5.0e8f) ? hv : 0.f;
        }
        return;
    }
    for (int e = gtid; e < E; e += gsz) {
        float hs = __ldcg(&hbuf[p][sndr[e]]);
        hs = (hs > -5.0e8f) ? hs : 0.f;
        float hr = __ldcg(&hbuf[p][rcvr[e]]);
        hr = (hr > -5.0e8f) ? hr : 0.f;
        float dh = hs - hr;
        float q = dh * __powf(dh * dh + 1e-24f, -0.23f) / __powf(r_d[e], 0.54f);
        float pe = pump_d[e];
        if (pe != 0.f) q = 0.f;
        qtilde_d[e] = q;
        if (fabsf(pe) == 1.0f) qhat_d[e] = q;
    }
    gbar();
    for (int n = gtid; n < N; n += gsz) {
        int o = csr_off[n], c2 = csr_cnt[n];
        float s = 0.f;
        for (int i = 0; i < c2; i++) s += __ldcg(&qhat_d[csr_edge[o + i]]);
        dhat_d[n] = s;
    }
}

// ---------------- launch ----------------
extern "C" void kernel_launch(void* const* d_in, const int* in_sizes, int n_in,
                              void* d_out, int out_size) {
    const float* x     = (const float*)d_in[0];
    const float* ea    = (const float*)d_in[1];
    const float* Wni   = (const float*)d_in[2];
    const float* Wedge = (const float*)d_in[3];
    const float* Wz    = (const float*)d_in[4];
    const float* Wf    = (const float*)d_in[5];
    const float* We1   = (const float*)d_in[6];
    const float* We2   = (const float*)d_in[7];
    const float* Wn1   = (const float*)d_in[8];
    const float* Wn2   = (const float*)d_in[9];
    const int*   ei    = (const int*)d_in[10];

    int N  = in_sizes[0] / 5;
    int E  = in_sizes[10] / 2;
    int Eh = E / 2;
    const int* sndr = ei;
    const int* rcvr = ei + E;
    const int K = 3;  // r_iter=1 + n_iter=2 (fixed by dataset)
    const int TB = 256;
    int mNE = N > E ? N : E;

    cudaFuncSetAttribute(edge_mlp_tc<true>,  cudaFuncAttributeMaxDynamicSharedMemorySize, SMEM_MLP);
    cudaFuncSetAttribute(edge_mlp_tc<false>, cudaFuncAttributeMaxDynamicSharedMemorySize, SMEM_MLP);
    cudaFuncSetAttribute(node_mlp_tc<true>,  cudaFuncAttributeMaxDynamicSharedMemorySize, SMEM_MLP);
    cudaFuncSetAttribute(node_mlp_tc<false>, cudaFuncAttributeMaxDynamicSharedMemorySize, SMEM_MLP);
    cudaFuncSetAttribute(zbar_tc,            cudaFuncAttributeMaxDynamicSharedMemorySize, SMEM_ZB);

    pack_kernel<<<(mNE + TB - 1) / TB, TB>>>(x, ea, N, E, Eh);
    csr_count_kernel<<<(E + TB - 1) / TB, TB>>>(rcvr, E, N);
    csr_scan_kernel<<<1, 1024>>>(N);
    csr_fill_kernel<<<(E + TB - 1) / TB, TB>>>(rcvr, sndr, E);
    wprep_all<<<(WT_TOTAL + TB - 1) / TB, TB>>>(We1, We2, Wn1, Wn2, Wz);
    wcomb_kernel<<<6, 256>>>(We1, Wedge, Wni, Wn1);

    int gE = (E + 127) / 128;
    int gN = (N + 127) / 128;
    const int we1off[2] = {OFF_E1_0, OFF_E1_1};
    const int we2off[2] = {OFF_E2_0, OFF_E2_1};
    const int wn1off[2] = {OFF_N1_0, OFF_N1_1};
    const int wn2off[2] = {OFF_N2_0, OFF_N2_1};

    for (int k = 0; k < K; k++) {
        int gp = 0, zp = 0;
        for (int i = 0; i < 2; i++) {
            if (i == 0)
                edge_mlp_tc<true><<<gE, 256, SMEM_MLP>>>(we1off[i], we2off[i],
                                                         sndr, rcvr, gp, zp, 1 - zp, E);
            else
                edge_mlp_tc<false><<<gE, 256, SMEM_MLP>>>(we1off[i], we2off[i],
                                                          sndr, rcvr, gp, zp, 1 - zp, E);
            agg_kernel<<<(N * 32 + TB - 1) / TB, TB>>>(1 - zp, N);
            if (i == 0)
                node_mlp_tc<true><<<gN, 256, SMEM_MLP>>>(wn1off[i], wn2off[i], gp, 1 - gp, N);
            else
                node_mlp_tc<false><<<gN, 256, SMEM_MLP>>>(wn1off[i], wn2off[i], gp, 1 - gp, N);
            gp = 1 - gp;
            zp = 1 - zp;
        }
        zbar_tc<<<gE, 256, SMEM_ZB>>>(Wf, sndr, rcvr, gp, zp, E, Eh);
        heads_fused<<<HP_BLOCKS, 256>>>(sndr, rcvr, N, E, Eh, (k < K - 1) ? 1 : 0, (float*)d_out);
    }
}

// round 16
// speedup vs baseline: 1.4743x; 1.1752x over previous
#include <cuda_runtime.h>
#include <cuda_bf16.h>
#include <math.h>
#include <stdint.h>

#define NMAX 20000
#define EMAX 60000
#define EHMAX 30000
#define ML 128

// ---------------- scratch (static __device__ — no runtime alloc) ----------------
__device__ unsigned short g_hi[2][NMAX * ML], g_lo[2][NMAX * ML];
__device__ unsigned short z_hi[2][EMAX * ML], z_lo[2][EMAX * ML];
__device__ unsigned short agg_hi[NMAX * ML], agg_lo[NMAX * ML];
__device__ float dot_buf[EMAX];
__device__ float qhat_d[EMAX];
__device__ float qtilde_d[EMAX];
__device__ float qhatdir_d[EHMAX];
__device__ float dhat_d[NMAX];
__device__ float hbuf[2][NMAX];
__device__ float r_d[EMAX], pump_d[EMAX], c0_d[EMAX], c1_d[EMAX], c2_d[EMAX];
__device__ float hstar_d[NMAX], dstar_d[NMAX], resm_d[NMAX];
__device__ int   csr_off[NMAX], csr_cnt[NMAX], csr_cur[NMAX], csr_edge[EMAX];
__device__ int   csr_sndr_d[EMAX];
__device__ float csr_loss_d[EMAX];
__device__ int   known_cum;
__device__ int   nres_d;
__device__ unsigned int bar_cnt, bar_epoch;

// folded L0 weights (fp32)
__device__ float w1eff_e[8 * 128];   // x8 -> hidden for edge L0 stage 1
__device__ float wn1eff[3 * 128];    // x3 -> hidden for node L0 stage 1 (g half)
__device__ float vfold[2 * 384];     // Wz @ Wf halves: [h][k]

// transposed + split weights: [n][k] layout, bf16 hi / lo
#define WT_TOTAL 278528
__device__ unsigned short wt_hi[WT_TOTAL];
__device__ unsigned short wt_lo[WT_TOTAL];
#define OFF_E1_0 0
#define OFF_E1_1 49152
#define OFF_E2_0 98304
#define OFF_E2_1 114688
#define OFF_N1_0 131072
#define OFF_N1_1 163840
#define OFF_N2_0 196608
#define OFF_N2_1 212992
#define OFF_Z    229376

// ---------------- bf16 split helpers ----------------
__device__ __forceinline__ void split2(float v, unsigned short& h, unsigned short& l) {
    __nv_bfloat16 bh = __float2bfloat16_rn(v);
    h = __bfloat16_as_ushort(bh);
    float resid = v - __bfloat162float(bh);
    l = __bfloat16_as_ushort(__float2bfloat16_rn(resid));
}
__device__ __forceinline__ uint32_t bf16x2_pack(float hi, float lo) {
    uint32_t r;
    asm("cvt.rn.bf16x2.f32 %0, %1, %2;" : "=r"(r) : "f"(hi), "f"(lo));
    return r;
}
__device__ __forceinline__ void split2x2(float v0, float v1, uint32_t& hw, uint32_t& lw) {
    hw = bf16x2_pack(v1, v0);
    float h0 = __uint_as_float(hw << 16);
    float h1 = __uint_as_float(hw & 0xffff0000u);
    lw = bf16x2_pack(v1 - h1, v0 - h0);
}
__device__ __forceinline__ float us2f(unsigned short u) {
    return __uint_as_float((uint32_t)u << 16);
}

__device__ __forceinline__ void mma_bf16(float c[4], const uint32_t a[4], const uint32_t b[2]) {
    asm volatile(
        "mma.sync.aligned.m16n8k16.row.col.f32.bf16.bf16.f32 "
        "{%0,%1,%2,%3}, {%4,%5,%6,%7}, {%8,%9}, {%0,%1,%2,%3};\n"
        : "+f"(c[0]), "+f"(c[1]), "+f"(c[2]), "+f"(c[3])
        : "r"(a[0]), "r"(a[1]), "r"(a[2]), "r"(a[3]), "r"(b[0]), "r"(b[1]));
}

__device__ __forceinline__ void ldsm4(uint32_t* r, const unsigned short* p) {
    uint32_t a = (uint32_t)__cvta_generic_to_shared(p);
    asm volatile("ldmatrix.sync.aligned.m8n8.x4.shared.b16 {%0,%1,%2,%3}, [%4];"
                 : "=r"(r[0]), "=r"(r[1]), "=r"(r[2]), "=r"(r[3]) : "r"(a));
}

// ---- smem geometry ----
#define PA 40
#define PB 40
#define PH 136
#define A_U16 (128 * PA)
#define B_U16 (128 * PB)
#define H_U16 (128 * PH)
#define SMEM_MLP  ((4 * A_U16 + 4 * B_U16 + 2 * H_U16) * 2)

// one k16 step of split-bf16 mma using ldmatrix.x4 fragment loads
__device__ __forceinline__ void k16_step(
    float acc[4][4][4],
    const unsigned short* __restrict__ Ah_, const unsigned short* __restrict__ Al_,
    int pa, int ka,
    const unsigned short* __restrict__ Bh_, const unsigned short* __restrict__ Bl_,
    int kb, int wm, int wn, int lane)
{
    int l7 = lane & 7, lb3 = (lane >> 3) & 1, lb4 = lane >> 4;
    uint32_t ah[4][4], al[4][4], bh[4][2], bl[4][2];
    int arow = wm * 64 + l7 + lb3 * 8;
    int akof = ka + lb4 * 8;
#pragma unroll
    for (int mf = 0; mf < 4; mf++) {
        ldsm4(ah[mf], Ah_ + (arow + mf * 16) * pa + akof);
        ldsm4(al[mf], Al_ + (arow + mf * 16) * pa + akof);
    }
    int brow = wn * 32 + l7 + lb4 * 8;
    int bkof = kb + lb3 * 8;
#pragma unroll
    for (int h = 0; h < 2; h++) {
        uint32_t t[4];
        ldsm4(t, Bh_ + (brow + h * 16) * PB + bkof);
        bh[2 * h][0] = t[0]; bh[2 * h][1] = t[1];
        bh[2 * h + 1][0] = t[2]; bh[2 * h + 1][1] = t[3];
        ldsm4(t, Bl_ + (brow + h * 16) * PB + bkof);
        bl[2 * h][0] = t[0]; bl[2 * h][1] = t[1];
        bl[2 * h + 1][0] = t[2]; bl[2 * h + 1][1] = t[3];
    }
#pragma unroll
    for (int mf = 0; mf < 4; mf++)
#pragma unroll
        for (int nf = 0; nf < 4; nf++) {
            mma_bf16(acc[mf][nf], al[mf], bh[nf]);
            mma_bf16(acc[mf][nf], ah[mf], bl[nf]);
            mma_bf16(acc[mf][nf], ah[mf], bh[nf]);
        }
}

// ---------------- weight prep ----------------
__global__ void wprep_all(const float* __restrict__ We1, const float* __restrict__ We2,
                          const float* __restrict__ Wn1, const float* __restrict__ Wn2,
                          const float* __restrict__ Wz) {
    int i = blockIdx.x * blockDim.x + threadIdx.x;
    if (i >= WT_TOTAL) return;
    const float* W; int Kd, off, li;
    if (i < 98304)       { li = i;          W = We1; Kd = 384; off = OFF_E1_0;
                           if (li >= 49152) { W = We1 + 49152; off = OFF_E1_1; li -= 49152; } }
    else if (i < 131072) { li = i - 98304;  W = We2; Kd = 128; off = OFF_E2_0;
                           if (li >= 16384) { W = We2 + 16384; off = OFF_E2_1; li -= 16384; } }
    else if (i < 196608) { li = i - 131072; W = Wn1; Kd = 256; off = OFF_N1_0;
                           if (li >= 32768) { W = Wn1 + 32768; off = OFF_N1_1; li -= 32768; } }
    else if (i < 229376) { li = i - 196608; W = Wn2; Kd = 128; off = OFF_N2_0;
                           if (li >= 16384) { W = Wn2 + 16384; off = OFF_N2_1; li -= 16384; } }
    else                 { li = i - 229376; W = Wz;  Kd = 384; off = OFF_Z; }
    int k = li >> 7, n = li & 127;
    unsigned short h, l;
    split2(W[li], h, l);
    wt_hi[off + (size_t)n * Kd + k] = h;
    wt_lo[off + (size_t)n * Kd + k] = l;
}

// fold low-rank L0 inputs through layer-0 W1 matrices + zbar/Wf fold (fp32)
__global__ void wcomb_kernel(const float* __restrict__ We1, const float* __restrict__ Wedge,
                             const float* __restrict__ Wni, const float* __restrict__ Wn1,
                             const float* __restrict__ Wz, const float* __restrict__ Wf) {
    int i = blockIdx.x * blockDim.x + threadIdx.x;
    if (i < 1024) {
        int k = i >> 7, c = i & 127;
        float s = 0.f;
        if (k < 3) {
            for (int j = 0; j < 128; j++) s += Wni[k * 128 + j] * We1[j * 128 + c];
        } else if (k < 6) {
            int kk = k - 3;
            for (int j = 0; j < 128; j++) s += Wni[kk * 128 + j] * We1[(128 + j) * 128 + c];
        } else {
            int kk = k - 6;
            for (int j = 0; j < 128; j++) s += Wedge[kk * 128 + j] * We1[(256 + j) * 128 + c];
        }
        w1eff_e[i] = s;
    } else if (i < 1024 + 384) {
        int ii = i - 1024;
        int k = ii >> 7, c = ii & 127;
        float s = 0.f;
        for (int j = 0; j < 128; j++) s += Wni[k * 128 + j] * Wn1[j * 128 + c];
        wn1eff[ii] = s;
    } else if (i < 1024 + 384 + 768) {
        int ii = i - 1024 - 384;
        int h = ii / 384, k = ii % 384;
        float s = 0.f;
        for (int c = 0; c < 128; c++) s += Wz[k * 128 + c] * Wf[h * 128 + c];
        vfold[ii] = s;
    }
}

// ---------------- setup kernels ----------------
__global__ void pack_kernel(const float* __restrict__ x, const float* __restrict__ ea,
                            int N, int E, int Eh) {
    int i = blockIdx.x * blockDim.x + threadIdx.x;
    if (i == 0) nres_d = 0;
    if (i < E) {
        r_d[i]    = ea[i * 8 + 0];
        pump_d[i] = ea[i * 8 + 3];
        c0_d[i]   = ea[i * 8 + 4];
        c1_d[i]   = ea[i * 8 + 5];
        c2_d[i]   = ea[i * 8 + 6];
        qhat_d[i] = 0.f;
        qtilde_d[i] = 0.f;
        if (i < Eh) qhatdir_d[i] = 0.f;
    }
    if (i < N) {
        hstar_d[i] = x[i * 5 + 0];
        dstar_d[i] = x[i * 5 + 1];
        resm_d[i]  = x[i * 5 + 4];
        dhat_d[i]  = 0.f;
        csr_cnt[i] = 0;
    }
}

__global__ void csr_count_kernel(const int* __restrict__ rcvr, int E, int N) {
    int e = blockIdx.x * blockDim.x + threadIdx.x;
    if (e < E) atomicAdd(&csr_cnt[rcvr[e]], 1);
    if (e < N && resm_d[e] > 0.5f) atomicAdd(&nres_d, 1);
}

__global__ void csr_scan_kernel(int N) {
    __shared__ int wsum[32];
    int t = threadIdx.x;
    int C = (N + 1023) >> 10;
    int beg = t * C;
    int end = beg + C; if (end > N) end = N;
    int s = 0;
    for (int i = beg; i < end; i++) s += csr_cnt[i];
    int lane = t & 31, w = t >> 5;
    int v = s;
    for (int o = 1; o < 32; o <<= 1) {
        int u = __shfl_up_sync(0xffffffffu, v, o);
        if (lane >= o) v += u;
    }
    if (lane == 31) wsum[w] = v;
    __syncthreads();
    if (w == 0) {
        int vv = wsum[lane];
        for (int o = 1; o < 32; o <<= 1) {
            int u = __shfl_up_sync(0xffffffffu, vv, o);
            if (lane >= o) vv += u;
        }
        wsum[lane] = vv;
    }
    __syncthreads();
    int base = (w > 0 ? wsum[w - 1] : 0) + (v - s);
    int run = base;
    for (int i = beg; i < end; i++) {
        csr_off[i] = run;
        csr_cur[i] = run;
        run += csr_cnt[i];
    }
}

__global__ void csr_fill_kernel(const int* __restrict__ rcvr, const int* __restrict__ sndr, int E) {
    int e = blockIdx.x * blockDim.x + threadIdx.x;
    if (e < E) {
        int pos = atomicAdd(&csr_cur[rcvr[e]], 1);
        csr_edge[pos] = e;
        csr_sndr_d[pos] = sndr[e];
    }
}

// ---------------- edge MLP ----------------
template<bool L0>
__global__ __launch_bounds__(256, 1) void edge_mlp_tc(
    int w1off, int w2off,
    const int* __restrict__ sndr, const int* __restrict__ rcvr,
    int gp, int zin_p, int zout_p, int E) {
    extern __shared__ unsigned short smu[];
    unsigned short* Ah = smu;
    unsigned short* Al = smu + 2 * A_U16;
    unsigned short* Bh = smu + 4 * A_U16;
    unsigned short* Bl = smu + 4 * A_U16 + 2 * B_U16;
    unsigned short* Hh = smu + 4 * A_U16 + 4 * B_U16;
    unsigned short* Hl = Hh + H_U16;
    __shared__ float lsm[L0 ? 2048 : 1];

    int tid = threadIdx.x;
    int wid = tid >> 5, lane = tid & 31;
    int g = lane >> 2, tg = lane & 3;
    int wm = wid >> 2, wn = wid & 3;
    int row0 = blockIdx.x * 128;

    int r = tid >> 1;
    int kh = (tid & 1) * 16;
    int eix = row0 + r; if (eix >= E) eix = E - 1;
    int sr = sndr[eix], rr = rcvr[eix];

    const unsigned short* gh = g_hi[gp];
    const unsigned short* gl = g_lo[gp];
    const unsigned short* zh = z_hi[zin_p];
    const unsigned short* zl = z_lo[zin_p];

    float acc[4][4][4];
#pragma unroll
    for (int a = 0; a < 4; a++)
#pragma unroll
        for (int b = 0; b < 4; b++)
#pragma unroll
            for (int q = 0; q < 4; q++) acc[a][b][q] = 0.f;

    uint4 pa0, pa1, pa2, pa3, pb0, pb1, pb2, pb3;
    auto prefA = [&](int s) {
        int kk = s * 32 + kh;
        const unsigned short *hs, *ls; size_t base;
        if (kk < 128)      { hs = gh; ls = gl; base = (size_t)sr * ML + kk; }
        else if (kk < 256) { hs = gh; ls = gl; base = (size_t)rr * ML + (kk - 128); }
        else               { hs = zh; ls = zl; base = (size_t)eix * ML + (kk - 256); }
        pa0 = *(const uint4*)(hs + base);
        pa1 = *(const uint4*)(hs + base + 8);
        pa2 = *(const uint4*)(ls + base);
        pa3 = *(const uint4*)(ls + base + 8);
    };
    auto prefB = [&](int s, int woff, int Kd) {
        int kk = s * 32 + kh;
        const unsigned short* p = wt_hi + woff + (size_t)r * Kd + kk;
        const unsigned short* q = wt_lo + woff + (size_t)r * Kd + kk;
        pb0 = *(const uint4*)p;
        pb1 = *(const uint4*)(p + 8);
        pb2 = *(const uint4*)q;
        pb3 = *(const uint4*)(q + 8);
    };
    auto commitA = [&](int b) {
        unsigned short* a = Ah + b * A_U16 + r * PA + kh;
        *(uint4*)a = pa0; *(uint4*)(a + 8) = pa1;
        unsigned short* a2 = Al + b * A_U16 + r * PA + kh;
        *(uint4*)a2 = pa2; *(uint4*)(a2 + 8) = pa3;
    };
    auto commitB = [&](int b) {
        unsigned short* d0 = Bh + b * B_U16 + r * PB + kh;
        *(uint4*)d0 = pb0; *(uint4*)(d0 + 8) = pb1;
        unsigned short* d1 = Bl + b * B_U16 + r * PB + kh;
        *(uint4*)d1 = pb2; *(uint4*)(d1 + 8) = pb3;
    };

    if (L0) {
        // stage 1 (folded, fp32): acc = x8 @ w1eff_e, K = 8
        float* w1e = lsm;
        float* x8s = lsm + 1024;
        for (int j = tid; j < 1024; j += 256) w1e[j] = w1eff_e[j];
        if ((tid & 1) == 0) {
            x8s[r * 8 + 0] = dhat_d[sr];
            x8s[r * 8 + 1] = dstar_d[sr];
            x8s[r * 8 + 2] = resm_d[sr];
            x8s[r * 8 + 3] = dhat_d[rr];
            x8s[r * 8 + 4] = dstar_d[rr];
            x8s[r * 8 + 5] = resm_d[rr];
            x8s[r * 8 + 6] = qtilde_d[eix];
            x8s[r * 8 + 7] = qhat_d[eix];
        }
        __syncthreads();
#pragma unroll
        for (int mf = 0; mf < 4; mf++) {
            int r0 = wm * 64 + mf * 16 + g;
            float xa[8], xb[8];
#pragma unroll
            for (int k = 0; k < 8; k++) { xa[k] = x8s[r0 * 8 + k]; xb[k] = x8s[(r0 + 8) * 8 + k]; }
#pragma unroll
            for (int nf = 0; nf < 4; nf++) {
                int c = wn * 32 + nf * 8 + tg * 2;
                float s00 = 0.f, s01 = 0.f, s10 = 0.f, s11 = 0.f;
#pragma unroll
                for (int k = 0; k < 8; k++) {
                    float w0 = w1e[k * 128 + c], w1 = w1e[k * 128 + c + 1];
                    s00 += xa[k] * w0; s01 += xa[k] * w1;
                    s10 += xb[k] * w0; s11 += xb[k] * w1;
                }
                acc[mf][nf][0] = s00; acc[mf][nf][1] = s01;
                acc[mf][nf][2] = s10; acc[mf][nf][3] = s11;
            }
        }
    } else {
        prefA(0); prefB(0, w1off, 384);
        commitA(0); commitB(0);
        __syncthreads();
        for (int s = 0; s < 12; s++) {
            int b = s & 1;
            if (s < 11) { prefA(s + 1); prefB(s + 1, w1off, 384); }
            k16_step(acc, Ah + b * A_U16, Al + b * A_U16, PA, 0,
                     Bh + b * B_U16, Bl + b * B_U16, 0, wm, wn, lane);
            k16_step(acc, Ah + b * A_U16, Al + b * A_U16, PA, 16,
                     Bh + b * B_U16, Bl + b * B_U16, 16, wm, wn, lane);
            if (s < 11) { commitA((s + 1) & 1); commitB((s + 1) & 1); }
            __syncthreads();
        }
    }
    // relu -> H (split bf16), reset acc
#pragma unroll
    for (int mf = 0; mf < 4; mf++) {
        int r0 = wm * 64 + mf * 16 + g;
#pragma unroll
        for (int nf = 0; nf < 4; nf++) {
            int c = wn * 32 + nf * 8 + tg * 2;
            uint32_t hw, lw;
            split2x2(fmaxf(acc[mf][nf][0], 0.f), fmaxf(acc[mf][nf][1], 0.f), hw, lw);
            *(uint32_t*)&Hh[r0 * PH + c] = hw;
            *(uint32_t*)&Hl[r0 * PH + c] = lw;
            split2x2(fmaxf(acc[mf][nf][2], 0.f), fmaxf(acc[mf][nf][3], 0.f), hw, lw);
            *(uint32_t*)&Hh[(r0 + 8) * PH + c] = hw;
            *(uint32_t*)&Hl[(r0 + 8) * PH + c] = lw;
            acc[mf][nf][0] = acc[mf][nf][1] = acc[mf][nf][2] = acc[mf][nf][3] = 0.f;
        }
    }
    // stage 2: K = 128, A = H, B pipelined
    prefB(0, w2off, 128);
    commitB(0);
    __syncthreads();
    for (int s = 0; s < 4; s++) {
        int b = s & 1;
        if (s < 3) prefB(s + 1, w2off, 128);
        k16_step(acc, Hh, Hl, PH, 32 * s,
                 Bh + b * B_U16, Bl + b * B_U16, 0, wm, wn, lane);
        k16_step(acc, Hh, Hl, PH, 32 * s + 16,
                 Bh + b * B_U16, Bl + b * B_U16, 16, wm, wn, lane);
        if (s < 3) commitB((s + 1) & 1);
        __syncthreads();
    }
    unsigned short* zoh = z_hi[zout_p];
    unsigned short* zol = z_lo[zout_p];
#pragma unroll
    for (int mf = 0; mf < 4; mf++) {
        int gr = row0 + wm * 64 + mf * 16 + g;
#pragma unroll
        for (int nf = 0; nf < 4; nf++) {
            int c = wn * 32 + nf * 8 + tg * 2;
            uint32_t hw, lw;
            if (gr < E) {
                split2x2(acc[mf][nf][0], acc[mf][nf][1], hw, lw);
                *(uint32_t*)&zoh[(size_t)gr * ML + c] = hw;
                *(uint32_t*)&zol[(size_t)gr * ML + c] = lw;
            }
            if (gr + 8 < E) {
                split2x2(acc[mf][nf][2], acc[mf][nf][3], hw, lw);
                *(uint32_t*)&zoh[(size_t)(gr + 8) * ML + c] = hw;
                *(uint32_t*)&zol[(size_t)(gr + 8) * ML + c] = lw;
            }
        }
    }
}

// ---------------- node MLP ----------------
template<bool L0>
__global__ __launch_bounds__(256, 1) void node_mlp_tc(
    int w1off, int w2off, int gp_in, int gp_out, int N) {
    extern __shared__ unsigned short smu[];
    unsigned short* Ah = smu;
    unsigned short* Al = smu + 2 * A_U16;
    unsigned short* Bh = smu + 4 * A_U16;
    unsigned short* Bl = smu + 4 * A_U16 + 2 * B_U16;
    unsigned short* Hh = smu + 4 * A_U16 + 4 * B_U16;
    unsigned short* Hl = Hh + H_U16;
    __shared__ float lsm[L0 ? (384 + 128 * 3) : 1];

    int tid = threadIdx.x;
    int wid = tid >> 5, lane = tid & 31;
    int g = lane >> 2, tg = lane & 3;
    int wm = wid >> 2, wn = wid & 3;
    int row0 = blockIdx.x * 128;

    int r = tid >> 1;
    int kh = (tid & 1) * 16;
    int er = row0 + r; if (er >= N) er = N - 1;

    if (L0) {
        for (int j = tid; j < 384; j += 256) lsm[j] = wn1eff[j];
        if ((tid & 1) == 0) {
            lsm[384 + r * 3 + 0] = dhat_d[er];
            lsm[384 + r * 3 + 1] = dstar_d[er];
            lsm[384 + r * 3 + 2] = resm_d[er];
        }
        __syncthreads();
    }

    const unsigned short* gh = g_hi[gp_in];
    const unsigned short* gl = g_lo[gp_in];

    float acc[4][4][4];
#pragma unroll
    for (int a = 0; a < 4; a++)
#pragma unroll
        for (int b = 0; b < 4; b++)
#pragma unroll
            for (int q = 0; q < 4; q++) acc[a][b][q] = 0.f;

    uint4 pa0, pa1, pa2, pa3, pb0, pb1, pb2, pb3;
    auto prefA = [&](int s) {
        int kk = s * 32 + kh;
        const unsigned short *hs, *ls; size_t base;
        if (kk < 128) { hs = gh; ls = gl; base = (size_t)er * ML + kk; }
        else          { hs = agg_hi; ls = agg_lo; base = (size_t)er * ML + (kk - 128); }
        pa0 = *(const uint4*)(hs + base);
        pa1 = *(const uint4*)(hs + base + 8);
        pa2 = *(const uint4*)(ls + base);
        pa3 = *(const uint4*)(ls + base + 8);
    };
    auto prefB = [&](int s, int woff, int Kd) {
        int kk = s * 32 + kh;
        const unsigned short* p = wt_hi + woff + (size_t)r * Kd + kk;
        const unsigned short* q = wt_lo + woff + (size_t)r * Kd + kk;
        pb0 = *(const uint4*)p;
        pb1 = *(const uint4*)(p + 8);
        pb2 = *(const uint4*)q;
        pb3 = *(const uint4*)(q + 8);
    };
    auto commitA = [&](int b) {
        unsigned short* a = Ah + b * A_U16 + r * PA + kh;
        *(uint4*)a = pa0; *(uint4*)(a + 8) = pa1;
        unsigned short* a2 = Al + b * A_U16 + r * PA + kh;
        *(uint4*)a2 = pa2; *(uint4*)(a2 + 8) = pa3;
    };
    auto commitB = [&](int b) {
        unsigned short* d0 = Bh + b * B_U16 + r * PB + kh;
        *(uint4*)d0 = pb0; *(uint4*)(d0 + 8) = pb1;
        unsigned short* d1 = Bl + b * B_U16 + r * PB + kh;
        *(uint4*)d1 = pb2; *(uint4*)(d1 + 8) = pb3;
    };

    // stage 1: K = 256 (L0: only agg half, s = 4..7)
    const int s0 = L0 ? 4 : 0;
    prefA(s0); prefB(s0, w1off, 256);
    commitA(s0 & 1); commitB(s0 & 1);
    __syncthreads();
    for (int s = s0; s < 8; s++) {
        int b = s & 1;
        if (s < 7) { prefA(s + 1); prefB(s + 1, w1off, 256); }
        k16_step(acc, Ah + b * A_U16, Al + b * A_U16, PA, 0,
                 Bh + b * B_U16, Bl + b * B_U16, 0, wm, wn, lane);
        k16_step(acc, Ah + b * A_U16, Al + b * A_U16, PA, 16,
                 Bh + b * B_U16, Bl + b * B_U16, 16, wm, wn, lane);
        if (s < 7) { commitA((s + 1) & 1); commitB((s + 1) & 1); }
        __syncthreads();
    }
#pragma unroll
    for (int mf = 0; mf < 4; mf++) {
        int r0 = wm * 64 + mf * 16 + g;
#pragma unroll
        for (int nf = 0; nf < 4; nf++) {
            int c = wn * 32 + nf * 8 + tg * 2;
            float v0 = acc[mf][nf][0], v1 = acc[mf][nf][1];
            float v2 = acc[mf][nf][2], v3 = acc[mf][nf][3];
            if (L0) {
                const float* x3a = lsm + 384 + r0 * 3;
                const float* x3b = lsm + 384 + (r0 + 8) * 3;
#pragma unroll
                for (int k = 0; k < 3; k++) {
                    float w0 = lsm[k * 128 + c], w1 = lsm[k * 128 + c + 1];
                    v0 += x3a[k] * w0; v1 += x3a[k] * w1;
                    v2 += x3b[k] * w0; v3 += x3b[k] * w1;
                }
            }
            uint32_t hw, lw;
            split2x2(fmaxf(v0, 0.f), fmaxf(v1, 0.f), hw, lw);
            *(uint32_t*)&Hh[r0 * PH + c] = hw;
            *(uint32_t*)&Hl[r0 * PH + c] = lw;
            split2x2(fmaxf(v2, 0.f), fmaxf(v3, 0.f), hw, lw);
            *(uint32_t*)&Hh[(r0 + 8) * PH + c] = hw;
            *(uint32_t*)&Hl[(r0 + 8) * PH + c] = lw;
            acc[mf][nf][0] = acc[mf][nf][1] = acc[mf][nf][2] = acc[mf][nf][3] = 0.f;
        }
    }
    // stage 2: K = 128
    prefB(0, w2off, 128);
    commitB(0);
    __syncthreads();
    for (int s = 0; s < 4; s++) {
        int b = s & 1;
        if (s < 3) prefB(s + 1, w2off, 128);
        k16_step(acc, Hh, Hl, PH, 32 * s,
                 Bh + b * B_U16, Bl + b * B_U16, 0, wm, wn, lane);
        k16_step(acc, Hh, Hl, PH, 32 * s + 16,
                 Bh + b * B_U16, Bl + b * B_U16, 16, wm, wn, lane);
        if (s < 3) commitB((s + 1) & 1);
        __syncthreads();
    }
    unsigned short* goh = g_hi[gp_out];
    unsigned short* gol = g_lo[gp_out];
#pragma unroll
    for (int mf = 0; mf < 4; mf++) {
        int gr = row0 + wm * 64 + mf * 16 + g;
#pragma unroll
        for (int nf = 0; nf < 4; nf++) {
            int c = wn * 32 + nf * 8 + tg * 2;
            uint32_t hw, lw;
            if (gr < N) {
                split2x2(acc[mf][nf][0], acc[mf][nf][1], hw, lw);
                *(uint32_t*)&goh[(size_t)gr * ML + c] = hw;
                *(uint32_t*)&gol[(size_t)gr * ML + c] = lw;
            }
            if (gr + 8 < N) {
                split2x2(acc[mf][nf][2], acc[mf][nf][3], hw, lw);
                *(uint32_t*)&goh[(size_t)(gr + 8) * ML + c] = hw;
                *(uint32_t*)&gol[(size_t)(gr + 8) * ML + c] = lw;
            }
        }
    }
}

// ---------------- zbar (folded): dot_buf[e] = [g_s,g_r,z] . vfold[half(e)] ----------------
__global__ __launch_bounds__(256) void zbar_dot(
    const int* __restrict__ sndr, const int* __restrict__ rcvr,
    int gp, int zp, int E, int Eh) {
    __shared__ float vf[768];
    int tid = threadIdx.x;
    for (int j = tid; j < 768; j += 256) vf[j] = vfold[j];
    __syncthreads();

    int e = blockIdx.x * 8 + (tid >> 5);
    if (e >= E) return;
    int lane = tid & 31;
    int sr = sndr[e], rr = rcvr[e];
    const float* v = vf + ((e < Eh) ? 0 : 384);
    const unsigned short* gh = g_hi[gp];
    const unsigned short* gl = g_lo[gp];
    const unsigned short* zh = z_hi[zp];
    const unsigned short* zl = z_lo[zp];

    int c0 = lane * 4;
    float acc = 0.f;
    {
        size_t b = (size_t)sr * ML + c0;
        uint2 vh = *(const uint2*)&gh[b];
        uint2 vl = *(const uint2*)&gl[b];
        acc += (us2f(vh.x & 0xffffu) + us2f(vl.x & 0xffffu)) * v[c0];
        acc += (us2f(vh.x >> 16)     + us2f(vl.x >> 16))     * v[c0 + 1];
        acc += (us2f(vh.y & 0xffffu) + us2f(vl.y & 0xffffu)) * v[c0 + 2];
        acc += (us2f(vh.y >> 16)     + us2f(vl.y >> 16))     * v[c0 + 3];
    }
    {
        size_t b = (size_t)rr * ML + c0;
        uint2 vh = *(const uint2*)&gh[b];
        uint2 vl = *(const uint2*)&gl[b];
        acc += (us2f(vh.x & 0xffffu) + us2f(vl.x & 0xffffu)) * v[128 + c0];
        acc += (us2f(vh.x >> 16)     + us2f(vl.x >> 16))     * v[128 + c0 + 1];
        acc += (us2f(vh.y & 0xffffu) + us2f(vl.y & 0xffffu)) * v[128 + c0 + 2];
        acc += (us2f(vh.y >> 16)     + us2f(vl.y >> 16))     * v[128 + c0 + 3];
    }
    {
        size_t b = (size_t)e * ML + c0;
        uint2 vh = *(const uint2*)&zh[b];
        uint2 vl = *(const uint2*)&zl[b];
        acc += (us2f(vh.x & 0xffffu) + us2f(vl.x & 0xffffu)) * v[256 + c0];
        acc += (us2f(vh.x >> 16)     + us2f(vl.x >> 16))     * v[256 + c0 + 1];
        acc += (us2f(vh.y & 0xffffu) + us2f(vl.y & 0xffffu)) * v[256 + c0 + 2];
        acc += (us2f(vh.y >> 16)     + us2f(vl.y >> 16))     * v[256 + c0 + 3];
    }
#pragma unroll
    for (int o = 16; o; o >>= 1) acc += __shfl_xor_sync(0xffffffffu, acc, o);
    if (lane == 0) dot_buf[e] = acc;
}

// ---------------- agg (segment max over split z, split output) ----------------
__global__ void agg_kernel(int zp, int N) {
    int t = blockIdx.x * blockDim.x + threadIdx.x;
    if (t >= N * 32) return;
    int n = t >> 5, c4 = (t & 31) * 4;
    const unsigned short* zh = z_hi[zp];
    const unsigned short* zl = z_lo[zp];
    int off = csr_off[n], cnt = csr_cnt[n];
    float m0 = -3.0e38f, m1 = -3.0e38f, m2 = -3.0e38f, m3 = -3.0e38f;
    for (int i = 0; i < cnt; i++) {
        size_t b = (size_t)csr_edge[off + i] * ML + c4;
        uint2 vh = *(const uint2*)&zh[b];
        uint2 vl = *(const uint2*)&zl[b];
        m0 = fmaxf(m0, __uint_as_float(vh.x << 16) + __uint_as_float(vl.x << 16));
        m1 = fmaxf(m1, __uint_as_float(vh.x & 0xffff0000u) + __uint_as_float(vl.x & 0xffff0000u));
        m2 = fmaxf(m2, __uint_as_float(vh.y << 16) + __uint_as_float(vl.y << 16));
        m3 = fmaxf(m3, __uint_as_float(vh.y & 0xffff0000u) + __uint_as_float(vl.y & 0xffff0000u));
    }
    if (cnt == 0) { m0 = m1 = m2 = m3 = 0.f; }
    uint32_t h0, l0, h1, l1;
    split2x2(m0, m1, h0, l0);
    split2x2(m2, m3, h1, l1);
    *(uint2*)&agg_hi[(size_t)n * ML + c4] = make_uint2(h0, h1);
    *(uint2*)&agg_lo[(size_t)n * ML + c4] = make_uint2(l0, l1);
}

// ---------------- fused heads (persistent grid) ----------------
#define HP_BLOCKS 148

__device__ __forceinline__ void gbar() {
    __syncthreads();
    if (threadIdx.x == 0) {
        unsigned int e = *(volatile unsigned int*)&bar_epoch;
        __threadfence();
        unsigned int a = atomicAdd(&bar_cnt, 1u);
        if (a == gridDim.x - 1) {
            bar_cnt = 0;
            __threadfence();
            atomicAdd(&bar_epoch, 1u);
        } else {
            while (*(volatile unsigned int*)&bar_epoch == e) { }
        }
    }
    __syncthreads();
}

__global__ __launch_bounds__(256) void heads_fused(
    const int* __restrict__ sndr, const int* __restrict__ rcvr,
    int N, int E, int Eh, int do_tail, float* __restrict__ out) {
    int gtid = blockIdx.x * blockDim.x + threadIdx.x;
    int gsz = gridDim.x * blockDim.x;
    int nres = *(volatile int*)&nres_d;

    for (int i = gtid; i < Eh; i += gsz) {
        float qd = qhatdir_d[i] + dot_buf[i] + dot_buf[i + Eh];
        float pd = pump_d[Eh + i];
        if (pd == 1.0f) qd = fminf(qd, 0.f);
        if (pd == 2.0f) qd = 0.f;
        qhatdir_d[i] = qd;
        qhat_d[i] = qd;
        qhat_d[i + Eh] = -qd;
    }
    for (int n = gtid; n < N; n += gsz)
        hbuf[0][n] = (resm_d[n] > 0.5f) ? hstar_d[n] : -1.0e30f;
    if (gtid == 0) known_cum = 0;
    gbar();

    for (int p = gtid; p < E; p += gsz) {
        int e = csr_edge[p];
        float q = __ldcg(&qhat_d[e]);
        float q2 = q * q + 1e-24f;
        float lp = r_d[e] * q * __powf(q2, 0.426f);
        float lpu = -(c0_d[e] - c1_d[e] * __powf(q2, c2_d[e] * 0.5f));
        csr_loss_d[p] = (pump_d[e] != 0.f) ? lpu : lp;
    }
    gbar();

    int off = 0, cnt = 0;
    if (gtid < N) { off = csr_off[gtid]; cnt = csr_cnt[gtid]; }
    int prev = 0;
    int p = 0;
    int stable = 0;
    for (int t = 0; t < 20; t++) {
        if (gtid < N) {
            float hv = hbuf[p][gtid];
            if (hv > -5.0e8f) {
                if (stable == 0) { hbuf[1 - p][gtid] = hv; stable = 1; }
            } else {
                float m = -3.0e38f;
                for (int i = off; i < off + cnt; i++) {
                    float hs = __ldcg(&hbuf[p][csr_sndr_d[i]]);
                    m = fmaxf(m, hs - csr_loss_d[i]);
                }
                if (m > -5.0e8f) {
                    hbuf[1 - p][gtid] = m;
                    atomicAdd(&known_cum, 1);
                } else {
                    hbuf[1 - p][gtid] = hv;
                }
            }
        }
        p = 1 - p;
        gbar();
        int c = *(volatile int*)&known_cum;
        if (c == prev) break;
        prev = c;
        if (c + nres >= N) break;
    }
    if (!do_tail) {
        for (int n = gtid; n < N; n += gsz) {
            float hv = hbuf[p][n];
            out[n] = (hv > -5.0e8f) ? hv : 0.f;
        }
        return;
    }
    for (int e = gtid; e < E; e += gsz) {
        float hs = __ldcg(&hbuf[p][sndr[e]]);
        hs = (hs > -5.0e8f) ? hs : 0.f;
        float hr = __ldcg(&hbuf[p][rcvr[e]]);
        hr = (hr > -5.0e8f) ? hr : 0.f;
        float dh = hs - hr;
        float q = dh * __powf(dh * dh + 1e-24f, -0.23f) / __powf(r_d[e], 0.54f);
        float pe = pump_d[e];
        if (pe != 0.f) q = 0.f;
        qtilde_d[e] = q;
        if (fabsf(pe) == 1.0f) qhat_d[e] = q;
    }
    gbar();
    for (int n = gtid; n < N; n += gsz) {
        int o = csr_off[n], c2 = csr_cnt[n];
        float s = 0.f;
        for (int i = 0; i < c2; i++) s += __ldcg(&qhat_d[csr_edge[o + i]]);
        dhat_d[n] = s;
    }
}

// ---------------- launch ----------------
extern "C" void kernel_launch(void* const* d_in, const int* in_sizes, int n_in,
                              void* d_out, int out_size) {
    const float* x     = (const float*)d_in[0];
    const float* ea    = (const float*)d_in[1];
    const float* Wni   = (const float*)d_in[2];
    const float* Wedge = (const float*)d_in[3];
    const float* Wz    = (const float*)d_in[4];
    const float* Wf    = (const float*)d_in[5];
    const float* We1   = (const float*)d_in[6];
    const float* We2   = (const float*)d_in[7];
    const float* Wn1   = (const float*)d_in[8];
    const float* Wn2   = (const float*)d_in[9];
    const int*   ei    = (const int*)d_in[10];

    int N  = in_sizes[0] / 5;
    int E  = in_sizes[10] / 2;
    int Eh = E / 2;
    const int* sndr = ei;
    const int* rcvr = ei + E;
    const int K = 3;  // r_iter=1 + n_iter=2 (fixed by dataset)
    const int TB = 256;
    int mNE = N > E ? N : E;

    cudaFuncSetAttribute(edge_mlp_tc<true>,  cudaFuncAttributeMaxDynamicSharedMemorySize, SMEM_MLP);
    cudaFuncSetAttribute(edge_mlp_tc<false>, cudaFuncAttributeMaxDynamicSharedMemorySize, SMEM_MLP);
    cudaFuncSetAttribute(node_mlp_tc<true>,  cudaFuncAttributeMaxDynamicSharedMemorySize, SMEM_MLP);
    cudaFuncSetAttribute(node_mlp_tc<false>, cudaFuncAttributeMaxDynamicSharedMemorySize, SMEM_MLP);

    pack_kernel<<<(mNE + TB - 1) / TB, TB>>>(x, ea, N, E, Eh);
    csr_count_kernel<<<(E + TB - 1) / TB, TB>>>(rcvr, E, N);
    csr_scan_kernel<<<1, 1024>>>(N);
    csr_fill_kernel<<<(E + TB - 1) / TB, TB>>>(rcvr, sndr, E);
    wprep_all<<<(WT_TOTAL + TB - 1) / TB, TB>>>(We1, We2, Wn1, Wn2, Wz);
    wcomb_kernel<<<9, 256>>>(We1, Wedge, Wni, Wn1, Wz, Wf);

    int gE = (E + 127) / 128;
    int gN = (N + 127) / 128;
    int gZ = (E + 7) / 8;
    const int we1off[2] = {OFF_E1_0, OFF_E1_1};
    const int we2off[2] = {OFF_E2_0, OFF_E2_1};
    const int wn1off[2] = {OFF_N1_0, OFF_N1_1};
    const int wn2off[2] = {OFF_N2_0, OFF_N2_1};

    for (int k = 0; k < K; k++) {
        int gp = 0, zp = 0;
        for (int i = 0; i < 2; i++) {
            if (i == 0)
                edge_mlp_tc<true><<<gE, 256, SMEM_MLP>>>(we1off[i], we2off[i],
                                                         sndr, rcvr, gp, zp, 1 - zp, E);
            else
                edge_mlp_tc<false><<<gE, 256, SMEM_MLP>>>(we1off[i], we2off[i],
                                                          sndr, rcvr, gp, zp, 1 - zp, E);
            agg_kernel<<<(N * 32 + TB - 1) / TB, TB>>>(1 - zp, N);
            if (i == 0)
                node_mlp_tc<true><<<gN, 256, SMEM_MLP>>>(wn1off[i], wn2off[i], gp, 1 - gp, N);
            else
                node_mlp_tc<false><<<gN, 256, SMEM_MLP>>>(wn1off[i], wn2off[i], gp, 1 - gp, N);
            gp = 1 - gp;
            zp = 1 - zp;
        }
        zbar_dot<<<gZ, 256>>>(sndr, rcvr, gp, zp, E, Eh);
        heads_fused<<<HP_BLOCKS, 256>>>(sndr, rcvr, N, E, Eh, (k < K - 1) ? 1 : 0, (float*)d_out);
    }
}